// round 4
// baseline (speedup 1.0000x reference)
#include <cuda_runtime.h>
#include <math.h>
#include <stdint.h>

// ---------------- problem constants ----------------
#define B_SZ   4096
#define LATENT 512
#define D_     6
#define M_     16
#define K_     12      // knots
#define NB_    16
#define R_     128
#define HID_   256
#define KIN    518     // LATENT + D
#define NP_    368     // M*(1+NB+D)
#define NK_    192     // M*K

// output layout (tuple flattened in order)
#define OFF_LOGITS 0ull
#define OFF_MU     65536ull
#define OFF_SIG    50397184ull
#define OFF_MASK   100728832ull
#define OFF_BW     101515264ull

// ---------------- scratch (no allocs allowed) ----------------
__device__ float g_H [B_SZ * HID_];  // pre-LN hidden
__device__ float g_A [B_SZ * HID_];  // elu(LN(h))
__device__ float g_S [B_SZ * HID_];  // situation
__device__ float g_P [B_SZ * NP_];   // raw head
__device__ float g_Kc[B_SZ * NK_];   // knot logits

// ---------------- fp32 tiled GEMM: C = A[BxK] @ W[KxN] + bias ----------
// BM=32, BN=64, KT=16, 256 threads, 2x4 thread tile.
// CONCAT=true: A is concat(ls[B x 512], intent[B x 6]) materialized on the fly.
template<bool CONCAT>
__global__ void __launch_bounds__(256)
gemm32x64_kernel(const float* __restrict__ A,
                 const float* __restrict__ A2,
                 const float* __restrict__ W,
                 const float* __restrict__ bias,
                 float* __restrict__ C,
                 int K, int N) {
    __shared__ float As[16][32];
    __shared__ float Ws[16][64];

    const int bm = blockIdx.y * 32;
    const int bn = blockIdx.x * 64;
    const int tid = threadIdx.x;
    const int tx = tid & 15;       // col group (x4)
    const int ty = tid >> 4;       // row group (x2)

    float acc[2][4];
#pragma unroll
    for (int i = 0; i < 2; i++)
#pragma unroll
        for (int j = 0; j < 4; j++) acc[i][j] = 0.f;

    for (int k0 = 0; k0 < K; k0 += 16) {
        // A tile: 32 rows x 16 k, k-major in smem
#pragma unroll
        for (int i = 0; i < 2; i++) {
            int idx = tid + i * 256;
            int r  = idx >> 4;
            int kc = idx & 15;
            int k  = k0 + kc;
            float v = 0.f;
            if (k < K) {
                if (CONCAT)
                    v = (k < LATENT) ? A [(size_t)(bm + r) * LATENT + k]
                                     : A2[(size_t)(bm + r) * D_ + (k - LATENT)];
                else
                    v = A[(size_t)(bm + r) * K + k];
            }
            As[kc][r] = v;
        }
        // W tile: 16 k x 64 n
#pragma unroll
        for (int i = 0; i < 4; i++) {
            int idx = tid + i * 256;
            int kr = idx >> 6;
            int c  = idx & 63;
            float v = 0.f;
            if ((k0 + kr) < K && (bn + c) < N) v = W[(size_t)(k0 + kr) * N + (bn + c)];
            Ws[kr][c] = v;
        }
        __syncthreads();

#pragma unroll
        for (int k = 0; k < 16; k++) {
            float2 a2 = *(const float2*)&As[k][ty * 2];
            float4 w4 = *(const float4*)&Ws[k][tx * 4];
            acc[0][0] += a2.x * w4.x; acc[0][1] += a2.x * w4.y;
            acc[0][2] += a2.x * w4.z; acc[0][3] += a2.x * w4.w;
            acc[1][0] += a2.y * w4.x; acc[1][1] += a2.y * w4.y;
            acc[1][2] += a2.y * w4.z; acc[1][3] += a2.y * w4.w;
        }
        __syncthreads();
    }

#pragma unroll
    for (int i = 0; i < 2; i++) {
        int r = bm + ty * 2 + i;
#pragma unroll
        for (int j = 0; j < 4; j++) {
            int c = bn + tx * 4 + j;
            if (c < N) C[(size_t)r * N + c] = acc[i][j] + bias[c];
        }
    }
}

// ---------------- LayerNorm + elu ----------------
__global__ void ln_elu_kernel(const float* __restrict__ g,
                              const float* __restrict__ bb) {
    const int b = blockIdx.x;
    const int t = threadIdx.x;   // 256
    float x = g_H[(size_t)b * HID_ + t];
    float v = x, v2 = x * x;
#pragma unroll
    for (int o = 16; o > 0; o >>= 1) {
        v  += __shfl_xor_sync(0xffffffffu, v,  o);
        v2 += __shfl_xor_sync(0xffffffffu, v2, o);
    }
    __shared__ float s1[8], s2[8];
    int wid = t >> 5, lane = t & 31;
    if (lane == 0) { s1[wid] = v; s2[wid] = v2; }
    __syncthreads();
    float tot = 0.f, tot2 = 0.f;
#pragma unroll
    for (int i = 0; i < 8; i++) { tot += s1[i]; tot2 += s2[i]; }
    float mu  = tot * (1.f / 256.f);
    float var = tot2 * (1.f / 256.f) - mu * mu;
    float y = (x - mu) * rsqrtf(var + 1e-5f) * g[t] + bb[t];
    g_A[(size_t)b * HID_ + t] = (y > 0.f) ? y : expm1f(y);
}

// ---------------- finalize: warp-per-mixture, one block per batch row ----
__global__ void __launch_bounds__(512)
finalize_kernel(const float* __restrict__ prev_vel,
                const float* __restrict__ intent,
                const float* __restrict__ basis,
                float* __restrict__ out) {
    const int b    = blockIdx.x;
    const int tid  = threadIdx.x;     // 512
    const int m    = tid >> 5;        // warp id = mixture index
    const int lane = tid & 31;

    __shared__ float basis_s[NB_ * K_ * D_];   // 1152
    __shared__ float pv_s[D_], it_s[D_];
    __shared__ float bw_s[M_][NB_];
    __shared__ float sig_s[M_][D_];
    __shared__ float knb[M_][K_ * D_];
    __shared__ int   cidx_s[M_][K_];
    __shared__ int   cnt_s[M_];

    for (int i = tid; i < NB_ * K_ * D_; i += 512) basis_s[i] = basis[i];
    if (tid == 0) {
        float n2 = 0.f, pv[D_];
#pragma unroll
        for (int d = 0; d < D_; d++) { pv[d] = prev_vel[(size_t)b * D_ + d]; n2 += pv[d] * pv[d]; }
        float inv = 1.f / (sqrtf(n2) + 1e-6f);
#pragma unroll
        for (int d = 0; d < D_; d++) {
            pv_s[d] = pv[d] * inv;
            it_s[d] = intent[(size_t)b * D_ + d];
        }
    }
    __syncthreads();

    // ---- heads (lanes 0..22) ----
    float r = 0.f;
    if (lane < 23) r = g_P[(size_t)b * NP_ + m * 23 + lane];
    if (lane == 0) {
        out[OFF_LOGITS + (size_t)b * M_ + m] = r;
    } else if (lane <= NB_) {
        float v = tanhf(r);
        bw_s[m][lane - 1] = v;
        out[OFF_BW + ((size_t)(b * M_ + m)) * NB_ + (lane - 1)] = v;
    } else if (lane < 23) {
        sig_s[m][lane - 1 - NB_] = expf(r) + 0.1f;
    }
    // ---- knot mask (lanes 0..11) ----
    float mv = 0.f;
    if (lane < K_) {
        float kv = g_Kc[(size_t)b * NK_ + m * K_ + lane];
        float sg = 1.f / (1.f + expf(-kv));
        mv = (lane == 0 || lane == K_ - 1) ? 1.0f : sg;
        out[OFF_MASK + ((size_t)(b * M_ + m)) * K_ + lane] = mv;
    }
    // mask compaction via ballot (stable order preserved)
    unsigned bal = __ballot_sync(0xffffffffu, (lane < K_) && (mv > 0.5f));
    if ((lane < K_) && (mv > 0.5f)) {
        int pos = __popc(bal & ((1u << lane) - 1u));
        cidx_s[m][pos] = lane;
    }
    if (lane == 0) cnt_s[m] = __popc(bal);
    __syncwarp();

    // ---- knots = tanh(raw) @ basis, knot0 subtracted ----
    for (int i = lane; i < K_ * D_; i += 32) {
        int d = i % D_;
        float acc = 0.f, acc0 = 0.f;
#pragma unroll
        for (int n = 0; n < NB_; n++) {
            float bwv = bw_s[m][n];
            acc  += bwv * basis_s[n * (K_ * D_) + i];
            acc0 += bwv * basis_s[n * (K_ * D_) + d];
        }
        knb[m][i] = acc - acc0;
    }
    __syncwarp();

    // ---- knot-1 alignment + last-knot intent shift (lane 0) ----
    if (lane == 0) {
        float n2 = 0.f, fs[D_];
#pragma unroll
        for (int d = 0; d < D_; d++) { fs[d] = knb[m][D_ + d]; n2 += fs[d] * fs[d]; }
        float mag = sqrtf(n2);
        float invm = 1.f / (mag + 1e-6f);
        float al[D_]; float an2 = 0.f;
#pragma unroll
        for (int d = 0; d < D_; d++) {
            float fn = fs[d] * invm;
            al[d] = 0.8f * pv_s[d] + 0.2f * fn;
            an2 += al[d] * al[d];
        }
        float inva = 1.f / (sqrtf(an2) + 1e-6f);
#pragma unroll
        for (int d = 0; d < D_; d++) knb[m][D_ + d] = al[d] * inva * mag;
#pragma unroll
        for (int d = 0; d < D_; d++) knb[m][(K_ - 1) * D_ + d] += 0.5f * it_s[d];
    }
    __syncwarp();

    // ---- Catmull-Rom spline + sigma broadcast ----
    const int count = cnt_s[m];
    float sgv[D_];
#pragma unroll
    for (int d = 0; d < D_; d++) sgv[d] = sig_s[m][d];

#pragma unroll
    for (int r0 = 0; r0 < R_; r0 += 32) {
        int t = r0 + lane;
        float xs = (float)t * (1.0f / 127.0f) * (float)(count - 1);
        int j = (int)floorf(xs);
        if (j > count - 2) j = count - 2;
        if (j < 0) j = 0;
        float u = xs - (float)j;
        float u2 = u * u, u3 = u2 * u;
        int i0 = cidx_s[m][(j - 1 > 0) ? j - 1 : 0];
        int i1 = cidx_s[m][j];
        int i2 = cidx_s[m][j + 1];
        int i3 = cidx_s[m][(j + 2 < count - 1) ? j + 2 : count - 1];
        size_t base_mu  = OFF_MU  + (((size_t)(b * M_ + m) * R_ + t) * D_);
        size_t base_sig = OFF_SIG + (((size_t)(b * M_ + m) * R_ + t) * D_);
#pragma unroll
        for (int d = 0; d < D_; d++) {
            float p0 = knb[m][i0 * D_ + d];
            float p1 = knb[m][i1 * D_ + d];
            float p2 = knb[m][i2 * D_ + d];
            float p3 = knb[m][i3 * D_ + d];
            float val = 0.5f * (2.f * p1
                                + (-p0 + p2) * u
                                + (2.f * p0 - 5.f * p1 + 4.f * p2 - p3) * u2
                                + (-p0 + 3.f * p1 - 3.f * p2 + p3) * u3);
            out[base_mu + d]  = val;
            out[base_sig + d] = sgv[d];
        }
    }
}

// ---------------- launcher ----------------
extern "C" void kernel_launch(void* const* d_in, const int* in_sizes, int n_in,
                              void* d_out, int out_size) {
    (void)in_sizes; (void)n_in; (void)out_size;
    const float* ls     = (const float*)d_in[0];
    const float* intent = (const float*)d_in[1];
    const float* pvel   = (const float*)d_in[2];
    const float* W1     = (const float*)d_in[3];
    const float* b1     = (const float*)d_in[4];
    const float* lng    = (const float*)d_in[5];
    const float* lnb    = (const float*)d_in[6];
    const float* W2     = (const float*)d_in[7];
    const float* b2     = (const float*)d_in[8];
    const float* Wp     = (const float*)d_in[9];
    const float* bp     = (const float*)d_in[10];
    const float* Wk     = (const float*)d_in[11];
    const float* bk     = (const float*)d_in[12];
    const float* basis  = (const float*)d_in[13];
    float* out = (float*)d_out;

    float *pH, *pA, *pS, *pP, *pK;
    cudaGetSymbolAddress((void**)&pH, g_H);
    cudaGetSymbolAddress((void**)&pA, g_A);
    cudaGetSymbolAddress((void**)&pS, g_S);
    cudaGetSymbolAddress((void**)&pP, g_P);
    cudaGetSymbolAddress((void**)&pK, g_Kc);

    // 1) H = concat(ls, intent) @ W1 + b1   (concat fused into A-load)
    gemm32x64_kernel<true><<<dim3(HID_ / 64, B_SZ / 32), 256>>>(ls, intent, W1, b1, pH, KIN, HID_);
    // 2) A = elu(LN(H))
    ln_elu_kernel<<<B_SZ, 256>>>(lng, lnb);
    // 3) S = A @ W2 + b2
    gemm32x64_kernel<false><<<dim3(HID_ / 64, B_SZ / 32), 256>>>(pA, nullptr, W2, b2, pS, HID_, HID_);
    // 4) P = S @ Wp + bp
    gemm32x64_kernel<false><<<dim3((NP_ + 63) / 64, B_SZ / 32), 256>>>(pS, nullptr, Wp, bp, pP, HID_, NP_);
    // 5) Kc = S @ Wk + bk
    gemm32x64_kernel<false><<<dim3(NK_ / 64, B_SZ / 32), 256>>>(pS, nullptr, Wk, bk, pK, HID_, NK_);
    // 6) heads + knots + spline + all outputs (warp per mixture)
    finalize_kernel<<<B_SZ, 512>>>(pvel, intent, basis, out);
}

// round 5
// speedup vs baseline: 1.4315x; 1.4315x over previous
#include <cuda_runtime.h>
#include <math.h>
#include <stdint.h>

// ---------------- problem constants ----------------
#define B_SZ   4096
#define LATENT 512
#define D_     6
#define M_     16
#define K_     12      // knots
#define NB_    16
#define R_     128
#define HID_   256
#define KIN    518     // LATENT + D
#define NP_    368     // M*(1+NB+D)
#define NK_    192     // M*K
#define BM_TOT (B_SZ * M_)   // 65536

// output layout (tuple flattened in order)
#define OFF_LOGITS 0ull
#define OFF_MU     65536ull
#define OFF_SIG    50397184ull
#define OFF_MASK   100728832ull
#define OFF_BW     101515264ull

// ---------------- scratch (no allocs allowed) ----------------
__device__ float g_H [B_SZ * HID_];  // pre-LN hidden
__device__ float g_A [B_SZ * HID_];  // elu(LN(h))
__device__ float g_S [B_SZ * HID_];  // situation
__device__ float g_P [B_SZ * NP_];   // raw head
__device__ float g_Kc[B_SZ * NK_];   // knot logits
__device__ float g_kn[BM_TOT * K_ * D_]; // fixed-up knots (72 per bm)
__device__ float g_sg[BM_TOT * D_];      // sigmas (6 per bm)
__device__ int   g_cx[BM_TOT * 16];      // cidx[0..11], [12]=count

// =====================================================================
// GEMM: C = A[BxK] @ W[KxN] + bias.  BM=64, BN=64, KT=16, 256 threads,
// 4x4 thread tile, double-buffered smem with register staging.
// CONCAT=true: A = concat(ls[Bx512], intent[Bx6]) materialized on the fly.
// =====================================================================
template<bool CONCAT>
__device__ __forceinline__ void g_loadA(const float* __restrict__ A,
                                        const float* __restrict__ A2,
                                        int bm, int k0, int K, int tid,
                                        float ar[4]) {
#pragma unroll
    for (int i = 0; i < 4; i++) {
        int idx = tid + i * 256;
        int r  = idx >> 4;
        int kc = idx & 15;
        int k  = k0 + kc;
        float v = 0.f;
        if (k < K) {
            if (CONCAT)
                v = (k < LATENT) ? A [(size_t)(bm + r) * LATENT + k]
                                 : A2[(size_t)(bm + r) * D_ + (k - LATENT)];
            else
                v = A[(size_t)(bm + r) * K + k];
        }
        ar[i] = v;
    }
}

__device__ __forceinline__ void g_loadW(const float* __restrict__ W,
                                        int bn, int k0, int K, int N, int tid,
                                        float wr[4]) {
#pragma unroll
    for (int i = 0; i < 4; i++) {
        int idx = tid + i * 256;
        int kr = idx >> 6;
        int c  = idx & 63;
        int k  = k0 + kr;
        float v = 0.f;
        if (k < K && (bn + c) < N) v = W[(size_t)k * N + (bn + c)];
        wr[i] = v;
    }
}

__device__ __forceinline__ void s_store(float (*As)[64], float (*Ws)[64],
                                        int tid, const float ar[4], const float wr[4]) {
#pragma unroll
    for (int i = 0; i < 4; i++) {
        int idx = tid + i * 256;
        As[idx & 15][idx >> 4] = ar[i];
    }
#pragma unroll
    for (int i = 0; i < 4; i++) {
        int idx = tid + i * 256;
        Ws[idx >> 6][idx & 63] = wr[i];
    }
}

template<bool CONCAT>
__global__ void __launch_bounds__(256)
gemm_db_kernel(const float* __restrict__ A,
               const float* __restrict__ A2,
               const float* __restrict__ W,
               const float* __restrict__ bias,
               float* __restrict__ C,
               int K, int N) {
    __shared__ float As[2][16][64];
    __shared__ float Ws[2][16][64];

    const int bm  = blockIdx.y * 64;
    const int bn  = blockIdx.x * 64;
    const int tid = threadIdx.x;
    const int tx  = tid & 15;
    const int ty  = tid >> 4;

    float acc[4][4];
#pragma unroll
    for (int i = 0; i < 4; i++)
#pragma unroll
        for (int j = 0; j < 4; j++) acc[i][j] = 0.f;

    float ar[4], wr[4];
    g_loadA<CONCAT>(A, A2, bm, 0, K, tid, ar);
    g_loadW(W, bn, 0, K, N, tid, wr);
    s_store(As[0], Ws[0], tid, ar, wr);
    __syncthreads();

    const int nT = (K + 15) >> 4;
    for (int t = 0; t < nT; t++) {
        const int cur = t & 1;
        const bool more = (t + 1 < nT);
        if (more) {
            g_loadA<CONCAT>(A, A2, bm, (t + 1) * 16, K, tid, ar);
            g_loadW(W, bn, (t + 1) * 16, K, N, tid, wr);
        }
#pragma unroll
        for (int k = 0; k < 16; k++) {
            float4 a4 = *(const float4*)&As[cur][k][ty * 4];
            float4 w4 = *(const float4*)&Ws[cur][k][tx * 4];
            acc[0][0] += a4.x * w4.x; acc[0][1] += a4.x * w4.y; acc[0][2] += a4.x * w4.z; acc[0][3] += a4.x * w4.w;
            acc[1][0] += a4.y * w4.x; acc[1][1] += a4.y * w4.y; acc[1][2] += a4.y * w4.z; acc[1][3] += a4.y * w4.w;
            acc[2][0] += a4.z * w4.x; acc[2][1] += a4.z * w4.y; acc[2][2] += a4.z * w4.z; acc[2][3] += a4.z * w4.w;
            acc[3][0] += a4.w * w4.x; acc[3][1] += a4.w * w4.y; acc[3][2] += a4.w * w4.z; acc[3][3] += a4.w * w4.w;
        }
        if (more) {
            s_store(As[cur ^ 1], Ws[cur ^ 1], tid, ar, wr);
            __syncthreads();
        }
    }

#pragma unroll
    for (int i = 0; i < 4; i++) {
        int r = bm + ty * 4 + i;
#pragma unroll
        for (int j = 0; j < 4; j++) {
            int c = bn + tx * 4 + j;
            if (c < N) C[(size_t)r * N + c] = acc[i][j] + bias[c];
        }
    }
}

// ---------------- LayerNorm + elu ----------------
__global__ void ln_elu_kernel(const float* __restrict__ g,
                              const float* __restrict__ bb) {
    const int b = blockIdx.x;
    const int t = threadIdx.x;   // 256
    float x = g_H[(size_t)b * HID_ + t];
    float v = x, v2 = x * x;
#pragma unroll
    for (int o = 16; o > 0; o >>= 1) {
        v  += __shfl_xor_sync(0xffffffffu, v,  o);
        v2 += __shfl_xor_sync(0xffffffffu, v2, o);
    }
    __shared__ float s1[8], s2[8];
    int wid = t >> 5, lane = t & 31;
    if (lane == 0) { s1[wid] = v; s2[wid] = v2; }
    __syncthreads();
    float tot = 0.f, tot2 = 0.f;
#pragma unroll
    for (int i = 0; i < 8; i++) { tot += s1[i]; tot2 += s2[i]; }
    float mu  = tot * (1.f / 256.f);
    float var = tot2 * (1.f / 256.f) - mu * mu;
    float y = (x - mu) * rsqrtf(var + 1e-5f) * g[t] + bb[t];
    g_A[(size_t)b * HID_ + t] = (y > 0.f) ? y : expm1f(y);
}

// =====================================================================
// Stage 1: heads + knot einsum + fixups + mask compaction.
// One block per batch row, one warp per mixture. Writes logits/mask/bw
// outputs and knots/sigma/cidx scratch.
// =====================================================================
__global__ void __launch_bounds__(512)
heads_kernel(const float* __restrict__ prev_vel,
             const float* __restrict__ intent,
             const float* __restrict__ basis,
             float* __restrict__ out) {
    const int b    = blockIdx.x;
    const int tid  = threadIdx.x;     // 512
    const int m    = tid >> 5;        // warp id = mixture index
    const int lane = tid & 31;
    const int bmix = b * M_ + m;

    __shared__ float basis_s[NB_ * K_ * D_];   // 1152
    __shared__ float pv_s[D_], it_s[D_];
    __shared__ float bw_s[M_][NB_];
    __shared__ float sig_s[M_][D_];
    __shared__ float knb[M_][K_ * D_];
    __shared__ int   cidx_s[M_][K_];

    for (int i = tid; i < NB_ * K_ * D_; i += 512) basis_s[i] = basis[i];
    if (tid == 0) {
        float n2 = 0.f, pv[D_];
#pragma unroll
        for (int d = 0; d < D_; d++) { pv[d] = prev_vel[(size_t)b * D_ + d]; n2 += pv[d] * pv[d]; }
        float inv = 1.f / (sqrtf(n2) + 1e-6f);
#pragma unroll
        for (int d = 0; d < D_; d++) {
            pv_s[d] = pv[d] * inv;
            it_s[d] = intent[(size_t)b * D_ + d];
        }
    }
    __syncthreads();

    // ---- heads (lanes 0..22) ----
    float r = 0.f;
    if (lane < 23) r = g_P[(size_t)b * NP_ + m * 23 + lane];
    if (lane == 0) {
        out[OFF_LOGITS + (size_t)bmix] = r;
    } else if (lane <= NB_) {
        float v = tanhf(r);
        bw_s[m][lane - 1] = v;
        out[OFF_BW + (size_t)bmix * NB_ + (lane - 1)] = v;
    } else if (lane < 23) {
        sig_s[m][lane - 1 - NB_] = expf(r) + 0.1f;
    }
    // ---- knot mask (lanes 0..11) ----
    if (lane < K_) cidx_s[m][lane] = 0;
    float mv = 0.f;
    if (lane < K_) {
        float kv = g_Kc[(size_t)b * NK_ + m * K_ + lane];
        float sg = 1.f / (1.f + expf(-kv));
        mv = (lane == 0 || lane == K_ - 1) ? 1.0f : sg;
        out[OFF_MASK + (size_t)bmix * K_ + lane] = mv;
    }
    // stable compaction via ballot
    unsigned bal = __ballot_sync(0xffffffffu, (lane < K_) && (mv > 0.5f));
    if ((lane < K_) && (mv > 0.5f)) {
        int pos = __popc(bal & ((1u << lane) - 1u));
        cidx_s[m][pos] = lane;
    }
    __syncwarp();

    // ---- knots = tanh(raw) @ basis, knot0 subtracted ----
    for (int i = lane; i < K_ * D_; i += 32) {
        int d = i % D_;
        float acc = 0.f, acc0 = 0.f;
#pragma unroll
        for (int n = 0; n < NB_; n++) {
            float bwv = bw_s[m][n];
            acc  += bwv * basis_s[n * (K_ * D_) + i];
            acc0 += bwv * basis_s[n * (K_ * D_) + d];
        }
        knb[m][i] = acc - acc0;
    }
    __syncwarp();

    // ---- knot-1 alignment + last-knot intent shift (lane 0) ----
    if (lane == 0) {
        float n2 = 0.f, fs[D_];
#pragma unroll
        for (int d = 0; d < D_; d++) { fs[d] = knb[m][D_ + d]; n2 += fs[d] * fs[d]; }
        float mag = sqrtf(n2);
        float invm = 1.f / (mag + 1e-6f);
        float al[D_]; float an2 = 0.f;
#pragma unroll
        for (int d = 0; d < D_; d++) {
            float fn = fs[d] * invm;
            al[d] = 0.8f * pv_s[d] + 0.2f * fn;
            an2 += al[d] * al[d];
        }
        float inva = 1.f / (sqrtf(an2) + 1e-6f);
#pragma unroll
        for (int d = 0; d < D_; d++) knb[m][D_ + d] = al[d] * inva * mag;
#pragma unroll
        for (int d = 0; d < D_; d++) knb[m][(K_ - 1) * D_ + d] += 0.5f * it_s[d];
    }
    __syncwarp();

    // ---- scratch writes for stage 2 ----
    for (int i = lane; i < K_ * D_; i += 32)
        g_kn[(size_t)bmix * (K_ * D_) + i] = knb[m][i];
    if (lane < D_)  g_sg[(size_t)bmix * D_ + lane] = sig_s[m][lane];
    if (lane < K_)  g_cx[bmix * 16 + lane] = cidx_s[m][lane];
    if (lane == K_) g_cx[bmix * 16 + 12]   = __popc(bal);
}

// =====================================================================
// Stage 2: Catmull-Rom spline + sigma broadcast. One block per (b,m),
// 192 threads; each thread writes one float4 to mu and one to sigma.
// =====================================================================
__global__ void __launch_bounds__(192)
spline_kernel(float* __restrict__ out) {
    const int bm  = blockIdx.x;       // 0..65535
    const int tid = threadIdx.x;      // 192

    __shared__ float kn_s[K_ * D_];   // 72
    __shared__ float sg_s[D_];
    __shared__ int   cx_s[K_];
    __shared__ int   cnt_s;

    if (tid < 72) kn_s[tid] = g_kn[(size_t)bm * 72 + tid];
    else if (tid < 78) sg_s[tid - 72] = g_sg[(size_t)bm * D_ + (tid - 72)];
    else if (tid < 90) cx_s[tid - 78] = g_cx[bm * 16 + (tid - 78)];
    else if (tid == 90) cnt_s = g_cx[bm * 16 + 12];
    __syncthreads();

    const int count = cnt_s;
    const float c1 = (1.0f / 127.0f) * (float)(count - 1);

    float4 muv, sgv;
    float* mup = &muv.x;
    float* sgp = &sgv.x;
#pragma unroll
    for (int e = 0; e < 4; e++) {
        int f = tid * 4 + e;          // 0..767
        int r = f / 6;
        int d = f - 6 * r;
        float xs = (float)r * c1;
        int j = (int)floorf(xs);
        if (j > count - 2) j = count - 2;
        if (j < 0) j = 0;
        float u = xs - (float)j;
        float u2 = u * u, u3 = u2 * u;
        int i0 = cx_s[(j - 1 > 0) ? j - 1 : 0];
        int i1 = cx_s[j];
        int i2 = cx_s[j + 1];
        int i3 = cx_s[(j + 2 < count - 1) ? j + 2 : count - 1];
        float p0 = kn_s[i0 * D_ + d];
        float p1 = kn_s[i1 * D_ + d];
        float p2 = kn_s[i2 * D_ + d];
        float p3 = kn_s[i3 * D_ + d];
        mup[e] = 0.5f * (2.f * p1
                         + (-p0 + p2) * u
                         + (2.f * p0 - 5.f * p1 + 4.f * p2 - p3) * u2
                         + (-p0 + 3.f * p1 - 3.f * p2 + p3) * u3);
        sgp[e] = sg_s[d];
    }

    size_t base = (size_t)bm * (R_ * D_) + tid * 4;   // 768 per bm, 16B aligned
    *(float4*)(out + OFF_MU  + base) = muv;
    *(float4*)(out + OFF_SIG + base) = sgv;
}

// ---------------- launcher ----------------
extern "C" void kernel_launch(void* const* d_in, const int* in_sizes, int n_in,
                              void* d_out, int out_size) {
    (void)in_sizes; (void)n_in; (void)out_size;
    const float* ls     = (const float*)d_in[0];
    const float* intent = (const float*)d_in[1];
    const float* pvel   = (const float*)d_in[2];
    const float* W1     = (const float*)d_in[3];
    const float* b1     = (const float*)d_in[4];
    const float* lng    = (const float*)d_in[5];
    const float* lnb    = (const float*)d_in[6];
    const float* W2     = (const float*)d_in[7];
    const float* b2     = (const float*)d_in[8];
    const float* Wp     = (const float*)d_in[9];
    const float* bp     = (const float*)d_in[10];
    const float* Wk     = (const float*)d_in[11];
    const float* bk     = (const float*)d_in[12];
    const float* basis  = (const float*)d_in[13];
    float* out = (float*)d_out;

    float *pH, *pA, *pS, *pP, *pK;
    cudaGetSymbolAddress((void**)&pH, g_H);
    cudaGetSymbolAddress((void**)&pA, g_A);
    cudaGetSymbolAddress((void**)&pS, g_S);
    cudaGetSymbolAddress((void**)&pP, g_P);
    cudaGetSymbolAddress((void**)&pK, g_Kc);

    // 1) H = concat(ls, intent) @ W1 + b1
    gemm_db_kernel<true><<<dim3(HID_ / 64, B_SZ / 64), 256>>>(ls, intent, W1, b1, pH, KIN, HID_);
    // 2) A = elu(LN(H))
    ln_elu_kernel<<<B_SZ, 256>>>(lng, lnb);
    // 3) S = A @ W2 + b2
    gemm_db_kernel<false><<<dim3(HID_ / 64, B_SZ / 64), 256>>>(pA, nullptr, W2, b2, pS, HID_, HID_);
    // 4) P = S @ Wp + bp
    gemm_db_kernel<false><<<dim3((NP_ + 63) / 64, B_SZ / 64), 256>>>(pS, nullptr, Wp, bp, pP, HID_, NP_);
    // 5) Kc = S @ Wk + bk
    gemm_db_kernel<false><<<dim3(NK_ / 64, B_SZ / 64), 256>>>(pS, nullptr, Wk, bk, pK, HID_, NK_);
    // 6) heads + knots + fixups (scratch) + logits/mask/bw outputs
    heads_kernel<<<B_SZ, 512>>>(pvel, intent, basis, out);
    // 7) spline + sigma broadcast (pure bandwidth)
    spline_kernel<<<BM_TOT, 192>>>(out);
}

// round 6
// speedup vs baseline: 1.9762x; 1.3805x over previous
#include <cuda_runtime.h>
#include <math.h>
#include <stdint.h>

// ---------------- problem constants ----------------
#define B_SZ   4096
#define LATENT 512
#define D_     6
#define M_     16
#define K_     12      // knots
#define NB_    16
#define R_     128
#define HID_   256
#define KIN    518     // LATENT + D
#define NP_    368     // M*(1+NB+D)
#define NK_    192     // M*K

// output layout (tuple flattened in order)
#define OFF_LOGITS 0ull
#define OFF_MU     65536ull
#define OFF_SIG    50397184ull
#define OFF_MASK   100728832ull
#define OFF_BW     101515264ull

// ---------------- scratch (no allocs allowed) ----------------
__device__ float g_H [B_SZ * HID_];  // pre-LN hidden
__device__ float g_A [B_SZ * HID_];  // elu(LN(h))
__device__ float g_S [B_SZ * HID_];  // situation
__device__ float g_P [B_SZ * NP_];   // raw head
__device__ float g_Kc[B_SZ * NK_];   // knot logits

// =====================================================================
// GEMM: C = A[BxK] @ W[KxN] + bias.  BM=64, BN=64, KT=16, 256 threads,
// 4x4 thread tile, double-buffered smem, float4 global loads.
// CONCAT=true: A = concat(ls[Bx512], intent[Bx6]) materialized on the fly.
// =====================================================================
template<bool CONCAT>
__device__ __forceinline__ void g_loadA(const float* __restrict__ A,
                                        const float* __restrict__ A2,
                                        int bm, int k0, int K, int tid,
                                        float ar[4]) {
    // thread -> row r = tid>>2, k-quad kq = (tid&3)*4
    const int r  = tid >> 2;
    const int kq = (tid & 3) * 4;
    const int k  = k0 + kq;
    if (CONCAT) {
        if (k + 15 - kq <= LATENT - 1 + 1 && k + 3 < LATENT) {   // whole quad in ls
            float4 v = *(const float4*)(A + (size_t)(bm + r) * LATENT + k);
            ar[0] = v.x; ar[1] = v.y; ar[2] = v.z; ar[3] = v.w;
        } else {
#pragma unroll
            for (int j = 0; j < 4; j++) {
                int kk = k + j;
                float v = 0.f;
                if (kk < KIN)
                    v = (kk < LATENT) ? A [(size_t)(bm + r) * LATENT + kk]
                                      : A2[(size_t)(bm + r) * D_ + (kk - LATENT)];
                ar[j] = v;
            }
        }
    } else {
        if (k + 3 < K) {
            float4 v = *(const float4*)(A + (size_t)(bm + r) * K + k);
            ar[0] = v.x; ar[1] = v.y; ar[2] = v.z; ar[3] = v.w;
        } else {
#pragma unroll
            for (int j = 0; j < 4; j++)
                ar[j] = (k + j < K) ? A[(size_t)(bm + r) * K + k + j] : 0.f;
        }
    }
}

__device__ __forceinline__ void g_loadW(const float* __restrict__ W,
                                        int bn, int k0, int K, int N, int tid,
                                        float wr[4]) {
    // thread -> k-row kr = tid>>4, col-quad c0 = (tid&15)*4
    const int kr = tid >> 4;
    const int c0 = (tid & 15) * 4;
    const int k  = k0 + kr;
    if (k < K && bn + c0 + 3 < N) {
        float4 v = *(const float4*)(W + (size_t)k * N + bn + c0);
        wr[0] = v.x; wr[1] = v.y; wr[2] = v.z; wr[3] = v.w;
    } else {
#pragma unroll
        for (int j = 0; j < 4; j++)
            wr[j] = (k < K && bn + c0 + j < N) ? W[(size_t)k * N + bn + c0 + j] : 0.f;
    }
}

__device__ __forceinline__ void s_store(float (*As)[64], float (*Ws)[64],
                                        int tid, const float ar[4], const float wr[4]) {
    const int r  = tid >> 2;
    const int kq = (tid & 3) * 4;
#pragma unroll
    for (int j = 0; j < 4; j++) As[kq + j][r] = ar[j];
    const int kr = tid >> 4;
    const int c0 = (tid & 15) * 4;
    *(float4*)&Ws[kr][c0] = make_float4(wr[0], wr[1], wr[2], wr[3]);
}

template<bool CONCAT>
__global__ void __launch_bounds__(256)
gemm_db_kernel(const float* __restrict__ A,
               const float* __restrict__ A2,
               const float* __restrict__ W,
               const float* __restrict__ bias,
               float* __restrict__ C,
               int K, int N) {
    __shared__ float As[2][16][64];
    __shared__ float Ws[2][16][64];

    const int bm  = blockIdx.y * 64;
    const int bn  = blockIdx.x * 64;
    const int tid = threadIdx.x;
    const int tx  = tid & 15;
    const int ty  = tid >> 4;

    float acc[4][4];
#pragma unroll
    for (int i = 0; i < 4; i++)
#pragma unroll
        for (int j = 0; j < 4; j++) acc[i][j] = 0.f;

    float ar[4], wr[4];
    g_loadA<CONCAT>(A, A2, bm, 0, K, tid, ar);
    g_loadW(W, bn, 0, K, N, tid, wr);
    s_store(As[0], Ws[0], tid, ar, wr);
    __syncthreads();

    const int nT = (K + 15) >> 4;
    for (int t = 0; t < nT; t++) {
        const int cur = t & 1;
        const bool more = (t + 1 < nT);
        if (more) {
            g_loadA<CONCAT>(A, A2, bm, (t + 1) * 16, K, tid, ar);
            g_loadW(W, bn, (t + 1) * 16, K, N, tid, wr);
        }
#pragma unroll
        for (int k = 0; k < 16; k++) {
            float4 a4 = *(const float4*)&As[cur][k][ty * 4];
            float4 w4 = *(const float4*)&Ws[cur][k][tx * 4];
            acc[0][0] += a4.x * w4.x; acc[0][1] += a4.x * w4.y; acc[0][2] += a4.x * w4.z; acc[0][3] += a4.x * w4.w;
            acc[1][0] += a4.y * w4.x; acc[1][1] += a4.y * w4.y; acc[1][2] += a4.y * w4.z; acc[1][3] += a4.y * w4.w;
            acc[2][0] += a4.z * w4.x; acc[2][1] += a4.z * w4.y; acc[2][2] += a4.z * w4.z; acc[2][3] += a4.z * w4.w;
            acc[3][0] += a4.w * w4.x; acc[3][1] += a4.w * w4.y; acc[3][2] += a4.w * w4.z; acc[3][3] += a4.w * w4.w;
        }
        if (more) {
            s_store(As[cur ^ 1], Ws[cur ^ 1], tid, ar, wr);
            __syncthreads();
        }
    }

#pragma unroll
    for (int i = 0; i < 4; i++) {
        int r = bm + ty * 4 + i;
#pragma unroll
        for (int j = 0; j < 4; j++) {
            int c = bn + tx * 4 + j;
            if (c < N) C[(size_t)r * N + c] = acc[i][j] + bias[c];
        }
    }
}

// ---------------- LayerNorm + elu ----------------
__global__ void ln_elu_kernel(const float* __restrict__ g,
                              const float* __restrict__ bb) {
    const int b = blockIdx.x;
    const int t = threadIdx.x;   // 256
    float x = g_H[(size_t)b * HID_ + t];
    float v = x, v2 = x * x;
#pragma unroll
    for (int o = 16; o > 0; o >>= 1) {
        v  += __shfl_xor_sync(0xffffffffu, v,  o);
        v2 += __shfl_xor_sync(0xffffffffu, v2, o);
    }
    __shared__ float s1[8], s2[8];
    int wid = t >> 5, lane = t & 31;
    if (lane == 0) { s1[wid] = v; s2[wid] = v2; }
    __syncthreads();
    float tot = 0.f, tot2 = 0.f;
#pragma unroll
    for (int i = 0; i < 8; i++) { tot += s1[i]; tot2 += s2[i]; }
    float mu  = tot * (1.f / 256.f);
    float var = tot2 * (1.f / 256.f) - mu * mu;
    float y = (x - mu) * rsqrtf(var + 1e-5f) * g[t] + bb[t];
    g_A[(size_t)b * HID_ + t] = (y > 0.f) ? y : expm1f(y);
}

// =====================================================================
// Fused epilogue: heads + knot einsum + fixups + spline, float4 stores.
// One block per batch row, one warp per mixture.
// =====================================================================
__global__ void __launch_bounds__(512)
epilogue_kernel(const float* __restrict__ prev_vel,
                const float* __restrict__ intent,
                const float* __restrict__ basis,
                float* __restrict__ out) {
    const int b    = blockIdx.x;
    const int tid  = threadIdx.x;     // 512
    const int m    = tid >> 5;        // warp id = mixture index
    const int lane = tid & 31;
    const int bmix = b * M_ + m;

    __shared__ float basis_s[NB_ * K_ * D_];   // 1152
    __shared__ float pv_s[D_], it_s[D_];
    __shared__ float bw_s[M_][NB_];
    __shared__ float sig_s[M_][D_ + 2];        // pad
    __shared__ float knb[M_][K_ * D_];
    __shared__ int   cidx_s[M_][K_];

    for (int i = tid; i < NB_ * K_ * D_; i += 512) basis_s[i] = basis[i];
    if (tid == 0) {
        float n2 = 0.f, pv[D_];
#pragma unroll
        for (int d = 0; d < D_; d++) { pv[d] = prev_vel[(size_t)b * D_ + d]; n2 += pv[d] * pv[d]; }
        float inv = 1.f / (sqrtf(n2) + 1e-6f);
#pragma unroll
        for (int d = 0; d < D_; d++) {
            pv_s[d] = pv[d] * inv;
            it_s[d] = intent[(size_t)b * D_ + d];
        }
    }
    __syncthreads();

    // ---- heads (lanes 0..22) ----
    float r = 0.f;
    if (lane < 23) r = g_P[(size_t)b * NP_ + m * 23 + lane];
    if (lane == 0) {
        out[OFF_LOGITS + (size_t)bmix] = r;
    } else if (lane <= NB_) {
        float v = tanhf(r);
        bw_s[m][lane - 1] = v;
        out[OFF_BW + (size_t)bmix * NB_ + (lane - 1)] = v;
    } else if (lane < 23) {
        sig_s[m][lane - 1 - NB_] = expf(r) + 0.1f;
    }
    // ---- knot mask (lanes 0..11) ----
    if (lane < K_) cidx_s[m][lane] = 0;
    float mv = 0.f;
    if (lane < K_) {
        float kv = g_Kc[(size_t)b * NK_ + m * K_ + lane];
        float sg = 1.f / (1.f + expf(-kv));
        mv = (lane == 0 || lane == K_ - 1) ? 1.0f : sg;
        out[OFF_MASK + (size_t)bmix * K_ + lane] = mv;
    }
    // stable compaction via ballot (warp-uniform bal)
    unsigned bal = __ballot_sync(0xffffffffu, (lane < K_) && (mv > 0.5f));
    if ((lane < K_) && (mv > 0.5f)) {
        int pos = __popc(bal & ((1u << lane) - 1u));
        cidx_s[m][pos] = lane;
    }
    __syncwarp();

    // ---- knots = tanh(raw) @ basis, knot0 subtracted ----
    for (int i = lane; i < K_ * D_; i += 32) {
        int d = i % D_;
        float acc = 0.f, acc0 = 0.f;
#pragma unroll
        for (int n = 0; n < NB_; n++) {
            float bwv = bw_s[m][n];
            acc  += bwv * basis_s[n * (K_ * D_) + i];
            acc0 += bwv * basis_s[n * (K_ * D_) + d];
        }
        knb[m][i] = acc - acc0;
    }
    __syncwarp();

    // ---- knot-1 alignment + last-knot intent shift (lane 0) ----
    if (lane == 0) {
        float n2 = 0.f, fs[D_];
#pragma unroll
        for (int d = 0; d < D_; d++) { fs[d] = knb[m][D_ + d]; n2 += fs[d] * fs[d]; }
        float mag = sqrtf(n2);
        float invm = 1.f / (mag + 1e-6f);
        float al[D_]; float an2 = 0.f;
#pragma unroll
        for (int d = 0; d < D_; d++) {
            float fn = fs[d] * invm;
            al[d] = 0.8f * pv_s[d] + 0.2f * fn;
            an2 += al[d] * al[d];
        }
        float inva = 1.f / (sqrtf(an2) + 1e-6f);
#pragma unroll
        for (int d = 0; d < D_; d++) knb[m][D_ + d] = al[d] * inva * mag;
#pragma unroll
        for (int d = 0; d < D_; d++) knb[m][(K_ - 1) * D_ + d] += 0.5f * it_s[d];
    }
    __syncwarp();

    // ---- Catmull-Rom spline + sigma, float4 stores ----
    const int count = __popc(bal);
    const float c1 = (1.0f / 127.0f) * (float)(count - 1);
    const size_t obase = (size_t)bmix * (R_ * D_);   // 768 floats per (b,m)

#pragma unroll
    for (int it = 0; it < 6; it++) {
        int f4 = it * 32 + lane;          // float4 index 0..191
        float4 muv, sgv;
        float* mup = &muv.x;
        float* sgp = &sgv.x;
#pragma unroll
        for (int e = 0; e < 4; e++) {
            int f = f4 * 4 + e;           // flat index 0..767
            int rr = f / 6;
            int d  = f - 6 * rr;
            float xs = (float)rr * c1;
            int j = (int)floorf(xs);
            if (j > count - 2) j = count - 2;
            if (j < 0) j = 0;
            float u = xs - (float)j;
            float u2 = u * u, u3 = u2 * u;
            int i0 = cidx_s[m][(j - 1 > 0) ? j - 1 : 0];
            int i1 = cidx_s[m][j];
            int i2 = cidx_s[m][j + 1];
            int i3 = cidx_s[m][(j + 2 < count - 1) ? j + 2 : count - 1];
            float p0 = knb[m][i0 * D_ + d];
            float p1 = knb[m][i1 * D_ + d];
            float p2 = knb[m][i2 * D_ + d];
            float p3 = knb[m][i3 * D_ + d];
            mup[e] = 0.5f * (2.f * p1
                             + (-p0 + p2) * u
                             + (2.f * p0 - 5.f * p1 + 4.f * p2 - p3) * u2
                             + (-p0 + 3.f * p1 - 3.f * p2 + p3) * u3);
            sgp[e] = sig_s[m][d];
        }
        *(float4*)(out + OFF_MU  + obase + (size_t)f4 * 4) = muv;
        *(float4*)(out + OFF_SIG + obase + (size_t)f4 * 4) = sgv;
    }
}

// ---------------- launcher ----------------
extern "C" void kernel_launch(void* const* d_in, const int* in_sizes, int n_in,
                              void* d_out, int out_size) {
    (void)in_sizes; (void)n_in; (void)out_size;
    const float* ls     = (const float*)d_in[0];
    const float* intent = (const float*)d_in[1];
    const float* pvel   = (const float*)d_in[2];
    const float* W1     = (const float*)d_in[3];
    const float* b1     = (const float*)d_in[4];
    const float* lng    = (const float*)d_in[5];
    const float* lnb    = (const float*)d_in[6];
    const float* W2     = (const float*)d_in[7];
    const float* b2     = (const float*)d_in[8];
    const float* Wp     = (const float*)d_in[9];
    const float* bp     = (const float*)d_in[10];
    const float* Wk     = (const float*)d_in[11];
    const float* bk     = (const float*)d_in[12];
    const float* basis  = (const float*)d_in[13];
    float* out = (float*)d_out;

    float *pH, *pA, *pS, *pP, *pK;
    cudaGetSymbolAddress((void**)&pH, g_H);
    cudaGetSymbolAddress((void**)&pA, g_A);
    cudaGetSymbolAddress((void**)&pS, g_S);
    cudaGetSymbolAddress((void**)&pP, g_P);
    cudaGetSymbolAddress((void**)&pK, g_Kc);

    // 1) H = concat(ls, intent) @ W1 + b1
    gemm_db_kernel<true><<<dim3(HID_ / 64, B_SZ / 64), 256>>>(ls, intent, W1, b1, pH, KIN, HID_);
    // 2) A = elu(LN(H))
    ln_elu_kernel<<<B_SZ, 256>>>(lng, lnb);
    // 3) S = A @ W2 + b2
    gemm_db_kernel<false><<<dim3(HID_ / 64, B_SZ / 64), 256>>>(pA, nullptr, W2, b2, pS, HID_, HID_);
    // 4) P = S @ Wp + bp
    gemm_db_kernel<false><<<dim3((NP_ + 63) / 64, B_SZ / 64), 256>>>(pS, nullptr, Wp, bp, pP, HID_, NP_);
    // 5) Kc = S @ Wk + bk
    gemm_db_kernel<false><<<dim3(NK_ / 64, B_SZ / 64), 256>>>(pS, nullptr, Wk, bk, pK, HID_, NK_);
    // 6) fused epilogue (heads + knots + spline + all outputs)
    epilogue_kernel<<<B_SZ, 512>>>(pvel, intent, basis, out);
}

// round 7
// speedup vs baseline: 2.1282x; 1.0769x over previous
#include <cuda_runtime.h>
#include <math.h>
#include <stdint.h>

// ---------------- problem constants ----------------
#define B_SZ   4096
#define LATENT 512
#define D_     6
#define M_     16
#define K_     12      // knots
#define NB_    16
#define R_     128
#define HID_   256
#define KIN    518     // LATENT + D
#define NP_    368     // M*(1+NB+D)
#define NK_    192     // M*K

// output layout (tuple flattened in order)
#define OFF_LOGITS 0ull
#define OFF_MU     65536ull
#define OFF_SIG    50397184ull
#define OFF_MASK   100728832ull
#define OFF_BW     101515264ull

// ---------------- scratch (no allocs allowed) ----------------
__device__ float g_H [B_SZ * HID_];  // pre-LN hidden
__device__ float g_A [B_SZ * HID_];  // elu(LN(h))
__device__ float g_S [B_SZ * HID_];  // situation
__device__ float g_P [B_SZ * NP_];   // raw head
__device__ float g_Kc[B_SZ * NK_];   // knot logits

// =====================================================================
// GEMM core: C = A[BxK] @ W[KxN] + bias.  BM=64, BN=64, KT=16,
// 256 threads, 4x4 thread tile, double-buffered smem, float4 loads.
// =====================================================================
template<bool CONCAT>
__device__ __forceinline__ void g_loadA(const float* __restrict__ A,
                                        const float* __restrict__ A2,
                                        int bm, int k0, int K, int tid,
                                        float ar[4]) {
    const int r  = tid >> 2;
    const int kq = (tid & 3) * 4;
    const int k  = k0 + kq;
    if (CONCAT) {
        if (k + 3 < LATENT) {
            float4 v = *(const float4*)(A + (size_t)(bm + r) * LATENT + k);
            ar[0] = v.x; ar[1] = v.y; ar[2] = v.z; ar[3] = v.w;
        } else {
#pragma unroll
            for (int j = 0; j < 4; j++) {
                int kk = k + j;
                float v = 0.f;
                if (kk < KIN)
                    v = (kk < LATENT) ? A [(size_t)(bm + r) * LATENT + kk]
                                      : A2[(size_t)(bm + r) * D_ + (kk - LATENT)];
                ar[j] = v;
            }
        }
    } else {
        if (k + 3 < K) {
            float4 v = *(const float4*)(A + (size_t)(bm + r) * K + k);
            ar[0] = v.x; ar[1] = v.y; ar[2] = v.z; ar[3] = v.w;
        } else {
#pragma unroll
            for (int j = 0; j < 4; j++)
                ar[j] = (k + j < K) ? A[(size_t)(bm + r) * K + k + j] : 0.f;
        }
    }
}

__device__ __forceinline__ void g_loadW(const float* __restrict__ W,
                                        int bn, int k0, int K, int N, int tid,
                                        float wr[4]) {
    const int kr = tid >> 4;
    const int c0 = (tid & 15) * 4;
    const int k  = k0 + kr;
    if (k < K && bn + c0 + 3 < N) {
        float4 v = *(const float4*)(W + (size_t)k * N + bn + c0);
        wr[0] = v.x; wr[1] = v.y; wr[2] = v.z; wr[3] = v.w;
    } else {
#pragma unroll
        for (int j = 0; j < 4; j++)
            wr[j] = (k < K && bn + c0 + j < N) ? W[(size_t)k * N + bn + c0 + j] : 0.f;
    }
}

__device__ __forceinline__ void s_store(float (*As)[64], float (*Ws)[64],
                                        int tid, const float ar[4], const float wr[4]) {
    const int r  = tid >> 2;
    const int kq = (tid & 3) * 4;
#pragma unroll
    for (int j = 0; j < 4; j++) As[kq + j][r] = ar[j];
    const int kr = tid >> 4;
    const int c0 = (tid & 15) * 4;
    *(float4*)&Ws[kr][c0] = make_float4(wr[0], wr[1], wr[2], wr[3]);
}

template<bool CONCAT>
__device__ __forceinline__ void gemm_core(const float* __restrict__ A,
                                          const float* __restrict__ A2,
                                          const float* __restrict__ W,
                                          const float* __restrict__ bias,
                                          float* __restrict__ C,
                                          int K, int N, int bm, int bn) {
    __shared__ float As[2][16][64];
    __shared__ float Ws[2][16][64];

    const int tid = threadIdx.x;
    const int tx  = tid & 15;
    const int ty  = tid >> 4;

    float acc[4][4];
#pragma unroll
    for (int i = 0; i < 4; i++)
#pragma unroll
        for (int j = 0; j < 4; j++) acc[i][j] = 0.f;

    float ar[4], wr[4];
    g_loadA<CONCAT>(A, A2, bm, 0, K, tid, ar);
    g_loadW(W, bn, 0, K, N, tid, wr);
    s_store(As[0], Ws[0], tid, ar, wr);
    __syncthreads();

    const int nT = (K + 15) >> 4;
    for (int t = 0; t < nT; t++) {
        const int cur = t & 1;
        const bool more = (t + 1 < nT);
        if (more) {
            g_loadA<CONCAT>(A, A2, bm, (t + 1) * 16, K, tid, ar);
            g_loadW(W, bn, (t + 1) * 16, K, N, tid, wr);
        }
#pragma unroll
        for (int k = 0; k < 16; k++) {
            float4 a4 = *(const float4*)&As[cur][k][ty * 4];
            float4 w4 = *(const float4*)&Ws[cur][k][tx * 4];
            acc[0][0] += a4.x * w4.x; acc[0][1] += a4.x * w4.y; acc[0][2] += a4.x * w4.z; acc[0][3] += a4.x * w4.w;
            acc[1][0] += a4.y * w4.x; acc[1][1] += a4.y * w4.y; acc[1][2] += a4.y * w4.z; acc[1][3] += a4.y * w4.w;
            acc[2][0] += a4.z * w4.x; acc[2][1] += a4.z * w4.y; acc[2][2] += a4.z * w4.z; acc[2][3] += a4.z * w4.w;
            acc[3][0] += a4.w * w4.x; acc[3][1] += a4.w * w4.y; acc[3][2] += a4.w * w4.z; acc[3][3] += a4.w * w4.w;
        }
        if (more) {
            s_store(As[cur ^ 1], Ws[cur ^ 1], tid, ar, wr);
            __syncthreads();
        }
    }

#pragma unroll
    for (int i = 0; i < 4; i++) {
        int r = bm + ty * 4 + i;
#pragma unroll
        for (int j = 0; j < 4; j++) {
            int c = bn + tx * 4 + j;
            if (c < N) C[(size_t)r * N + c] = acc[i][j] + bias[c];
        }
    }
}

template<bool CONCAT>
__global__ void __launch_bounds__(256)
gemm_db_kernel(const float* __restrict__ A,
               const float* __restrict__ A2,
               const float* __restrict__ W,
               const float* __restrict__ bias,
               float* __restrict__ C,
               int K, int N) {
    gemm_core<CONCAT>(A, A2, W, bias, C, K, N, blockIdx.y * 64, blockIdx.x * 64);
}

// Fused head GEMMs: P = S@Wp+bp (col tiles 0..5), Kc = S@Wk+bk (6..8).
__global__ void __launch_bounds__(256)
gemm_heads_kernel(const float* __restrict__ S,
                  const float* __restrict__ Wp, const float* __restrict__ bp,
                  const float* __restrict__ Wk, const float* __restrict__ bk) {
    const int ct = blockIdx.x;
    const int bm = blockIdx.y * 64;
    if (ct < 6)
        gemm_core<false>(S, nullptr, Wp, bp, g_P,  HID_, NP_, bm, ct * 64);
    else
        gemm_core<false>(S, nullptr, Wk, bk, g_Kc, HID_, NK_, bm, (ct - 6) * 64);
}

// ---------------- LayerNorm + elu ----------------
__global__ void ln_elu_kernel(const float* __restrict__ g,
                              const float* __restrict__ bb) {
    const int b = blockIdx.x;
    const int t = threadIdx.x;   // 256
    float x = g_H[(size_t)b * HID_ + t];
    float v = x, v2 = x * x;
#pragma unroll
    for (int o = 16; o > 0; o >>= 1) {
        v  += __shfl_xor_sync(0xffffffffu, v,  o);
        v2 += __shfl_xor_sync(0xffffffffu, v2, o);
    }
    __shared__ float s1[8], s2[8];
    int wid = t >> 5, lane = t & 31;
    if (lane == 0) { s1[wid] = v; s2[wid] = v2; }
    __syncthreads();
    float tot = 0.f, tot2 = 0.f;
#pragma unroll
    for (int i = 0; i < 8; i++) { tot += s1[i]; tot2 += s2[i]; }
    float mu  = tot * (1.f / 256.f);
    float var = tot2 * (1.f / 256.f) - mu * mu;
    float y = (x - mu) * rsqrtf(var + 1e-5f) * g[t] + bb[t];
    g_A[(size_t)b * HID_ + t] = (y > 0.f) ? y : expm1f(y);
}

// =====================================================================
// Fused epilogue: heads + knot einsum + fixups + spline.
// One block per batch row, one warp per mixture.
// Spline: per-r weights hoisted; lane owns 2 consecutive r values ->
// 3 aligned float4 mu stores; sigma float4 patterns are warp-uniform.
// =====================================================================
__global__ void __launch_bounds__(512)
epilogue_kernel(const float* __restrict__ prev_vel,
                const float* __restrict__ intent,
                const float* __restrict__ basis,
                float* __restrict__ out) {
    const int b    = blockIdx.x;
    const int tid  = threadIdx.x;     // 512
    const int m    = tid >> 5;        // warp id = mixture index
    const int lane = tid & 31;
    const int bmix = b * M_ + m;

    __shared__ float basis_s[NB_ * K_ * D_];   // 1152
    __shared__ float pv_s[D_], it_s[D_];
    __shared__ float bw_s[M_][NB_];
    __shared__ float sig_s[M_][D_ + 2];        // pad
    __shared__ float knb[M_][K_ * D_];
    __shared__ int   cidx_s[M_][K_];

    for (int i = tid; i < NB_ * K_ * D_; i += 512) basis_s[i] = basis[i];
    if (tid == 0) {
        float n2 = 0.f, pv[D_];
#pragma unroll
        for (int d = 0; d < D_; d++) { pv[d] = prev_vel[(size_t)b * D_ + d]; n2 += pv[d] * pv[d]; }
        float inv = 1.f / (sqrtf(n2) + 1e-6f);
#pragma unroll
        for (int d = 0; d < D_; d++) {
            pv_s[d] = pv[d] * inv;
            it_s[d] = intent[(size_t)b * D_ + d];
        }
    }
    __syncthreads();

    // ---- heads (lanes 0..22) ----
    float r = 0.f;
    if (lane < 23) r = g_P[(size_t)b * NP_ + m * 23 + lane];
    if (lane == 0) {
        out[OFF_LOGITS + (size_t)bmix] = r;
    } else if (lane <= NB_) {
        float v = tanhf(r);
        bw_s[m][lane - 1] = v;
        out[OFF_BW + (size_t)bmix * NB_ + (lane - 1)] = v;
    } else if (lane < 23) {
        sig_s[m][lane - 1 - NB_] = expf(r) + 0.1f;
    }
    // ---- knot mask (lanes 0..11) ----
    if (lane < K_) cidx_s[m][lane] = 0;
    float mv = 0.f;
    if (lane < K_) {
        float kv = g_Kc[(size_t)b * NK_ + m * K_ + lane];
        float sg = 1.f / (1.f + expf(-kv));
        mv = (lane == 0 || lane == K_ - 1) ? 1.0f : sg;
        out[OFF_MASK + (size_t)bmix * K_ + lane] = mv;
    }
    unsigned bal = __ballot_sync(0xffffffffu, (lane < K_) && (mv > 0.5f));
    if ((lane < K_) && (mv > 0.5f)) {
        int pos = __popc(bal & ((1u << lane) - 1u));
        cidx_s[m][pos] = lane;
    }
    __syncwarp();

    // ---- knots = tanh(raw) @ basis, knot0 subtracted ----
    for (int i = lane; i < K_ * D_; i += 32) {
        int d = i % D_;
        float acc = 0.f, acc0 = 0.f;
#pragma unroll
        for (int n = 0; n < NB_; n++) {
            float bwv = bw_s[m][n];
            acc  += bwv * basis_s[n * (K_ * D_) + i];
            acc0 += bwv * basis_s[n * (K_ * D_) + d];
        }
        knb[m][i] = acc - acc0;
    }
    __syncwarp();

    // ---- knot-1 alignment + last-knot intent shift (lane 0) ----
    if (lane == 0) {
        float n2 = 0.f, fs[D_];
#pragma unroll
        for (int d = 0; d < D_; d++) { fs[d] = knb[m][D_ + d]; n2 += fs[d] * fs[d]; }
        float mag = sqrtf(n2);
        float invm = 1.f / (mag + 1e-6f);
        float al[D_]; float an2 = 0.f;
#pragma unroll
        for (int d = 0; d < D_; d++) {
            float fn = fs[d] * invm;
            al[d] = 0.8f * pv_s[d] + 0.2f * fn;
            an2 += al[d] * al[d];
        }
        float inva = 1.f / (sqrtf(an2) + 1e-6f);
#pragma unroll
        for (int d = 0; d < D_; d++) knb[m][D_ + d] = al[d] * inva * mag;
#pragma unroll
        for (int d = 0; d < D_; d++) knb[m][(K_ - 1) * D_ + d] += 0.5f * it_s[d];
    }
    __syncwarp();

    // ---- Catmull-Rom spline + sigma ----
    const int count = __popc(bal);
    const float c1 = (1.0f / 127.0f) * (float)(count - 1);

    // warp-uniform sigma float4 patterns (d = flat_index mod 6; period 12)
    const float s0 = sig_s[m][0], s1v = sig_s[m][1], s2v = sig_s[m][2];
    const float s3 = sig_s[m][3], s4v = sig_s[m][4], s5v = sig_s[m][5];
    const float4 sgA = make_float4(s0, s1v, s2v, s3);
    const float4 sgB = make_float4(s4v, s5v, s0, s1v);
    const float4 sgC = make_float4(s2v, s3, s4v, s5v);

    const size_t obase = (size_t)bmix * (R_ * D_);   // 768 floats per (b,m)

#pragma unroll
    for (int it = 0; it < 2; it++) {
        const int idx = it * 32 + lane;    // 0..63, owns r = 2*idx, 2*idx+1
        float va[12];
#pragma unroll
        for (int h = 0; h < 2; h++) {
            const int rr = idx * 2 + h;
            float xs = (float)rr * c1;
            int j = (int)xs;               // xs >= 0 -> trunc == floor
            if (j > count - 2) j = count - 2;
            if (j < 0) j = 0;
            float u  = xs - (float)j;
            float u2 = u * u, u3 = u2 * u;
            float w0 = 0.5f * (-u3 + 2.f * u2 - u);
            float w1 = 0.5f * (3.f * u3 - 5.f * u2 + 2.f);
            float w2 = 0.5f * (-3.f * u3 + 4.f * u2 + u);
            float w3 = 0.5f * (u3 - u2);
            int i0 = cidx_s[m][(j - 1 > 0) ? j - 1 : 0];
            int i1 = cidx_s[m][j];
            int i2 = cidx_s[m][j + 1];
            int i3 = cidx_s[m][(j + 2 < count - 1) ? j + 2 : count - 1];
            const float* k0 = &knb[m][i0 * D_];
            const float* k1 = &knb[m][i1 * D_];
            const float* k2 = &knb[m][i2 * D_];
            const float* k3 = &knb[m][i3 * D_];
#pragma unroll
            for (int d = 0; d < D_; d++)
                va[h * D_ + d] = w0 * k0[d] + w1 * k1[d] + w2 * k2[d] + w3 * k3[d];
        }
        float4* mp = (float4*)(out + OFF_MU + obase + (size_t)idx * 12);
        mp[0] = make_float4(va[0], va[1], va[2],  va[3]);
        mp[1] = make_float4(va[4], va[5], va[6],  va[7]);
        mp[2] = make_float4(va[8], va[9], va[10], va[11]);
        float4* sp = (float4*)(out + OFF_SIG + obase + (size_t)idx * 12);
        sp[0] = sgA; sp[1] = sgB; sp[2] = sgC;
    }
}

// ---------------- launcher ----------------
extern "C" void kernel_launch(void* const* d_in, const int* in_sizes, int n_in,
                              void* d_out, int out_size) {
    (void)in_sizes; (void)n_in; (void)out_size;
    const float* ls     = (const float*)d_in[0];
    const float* intent = (const float*)d_in[1];
    const float* pvel   = (const float*)d_in[2];
    const float* W1     = (const float*)d_in[3];
    const float* b1     = (const float*)d_in[4];
    const float* lng    = (const float*)d_in[5];
    const float* lnb    = (const float*)d_in[6];
    const float* W2     = (const float*)d_in[7];
    const float* b2     = (const float*)d_in[8];
    const float* Wp     = (const float*)d_in[9];
    const float* bp     = (const float*)d_in[10];
    const float* Wk     = (const float*)d_in[11];
    const float* bk     = (const float*)d_in[12];
    const float* basis  = (const float*)d_in[13];
    float* out = (float*)d_out;

    float *pH, *pA, *pS;
    cudaGetSymbolAddress((void**)&pH, g_H);
    cudaGetSymbolAddress((void**)&pA, g_A);
    cudaGetSymbolAddress((void**)&pS, g_S);

    // 1) H = concat(ls, intent) @ W1 + b1
    gemm_db_kernel<true><<<dim3(HID_ / 64, B_SZ / 64), 256>>>(ls, intent, W1, b1, pH, KIN, HID_);
    // 2) A = elu(LN(H))
    ln_elu_kernel<<<B_SZ, 256>>>(lng, lnb);
    // 3) S = A @ W2 + b2
    gemm_db_kernel<false><<<dim3(HID_ / 64, B_SZ / 64), 256>>>(pA, nullptr, W2, b2, pS, HID_, HID_);
    // 4+5) P = S @ Wp + bp  and  Kc = S @ Wk + bk, fused launch
    gemm_heads_kernel<<<dim3(9, B_SZ / 64), 256>>>(pS, Wp, bp, Wk, bk);
    // 6) fused epilogue (heads + knots + spline + all outputs)
    epilogue_kernel<<<B_SZ, 512>>>(pvel, intent, basis, out);
}

// round 8
// speedup vs baseline: 2.4142x; 1.1344x over previous
#include <cuda_runtime.h>
#include <math.h>
#include <stdint.h>

// ---------------- problem constants ----------------
#define B_SZ   4096
#define LATENT 512
#define D_     6
#define M_     16
#define K_     12      // knots
#define NB_    16
#define R_     128
#define HID_   256
#define KIN    518     // LATENT + D
#define NP_    368     // M*(1+NB+D)
#define NK_    192     // M*K

// output layout (tuple flattened in order)
#define OFF_LOGITS 0ull
#define OFF_MU     65536ull
#define OFF_SIG    50397184ull
#define OFF_MASK   100728832ull
#define OFF_BW     101515264ull

// ---------------- scratch (no allocs allowed) ----------------
__device__ float g_H [B_SZ * HID_];  // pre-LN hidden
__device__ float g_A [B_SZ * HID_];  // elu(LN(h))
__device__ float g_S [B_SZ * HID_];  // situation
__device__ float g_P [B_SZ * NP_];   // raw head
__device__ float g_Kc[B_SZ * NK_];   // knot logits

// =====================================================================
// GEMM core: C = A[BxK] @ W[KxN] + bias.  BM=64, BN=64, KT=16,
// 256 threads, 4x4 thread tile, double-buffered smem, float4 loads.
// =====================================================================
template<bool CONCAT>
__device__ __forceinline__ void g_loadA(const float* __restrict__ A,
                                        const float* __restrict__ A2,
                                        int bm, int k0, int K, int tid,
                                        float ar[4]) {
    const int r  = tid >> 2;
    const int kq = (tid & 3) * 4;
    const int k  = k0 + kq;
    if (CONCAT) {
        if (k + 3 < LATENT) {
            float4 v = *(const float4*)(A + (size_t)(bm + r) * LATENT + k);
            ar[0] = v.x; ar[1] = v.y; ar[2] = v.z; ar[3] = v.w;
        } else {
#pragma unroll
            for (int j = 0; j < 4; j++) {
                int kk = k + j;
                float v = 0.f;
                if (kk < KIN)
                    v = (kk < LATENT) ? A [(size_t)(bm + r) * LATENT + kk]
                                      : A2[(size_t)(bm + r) * D_ + (kk - LATENT)];
                ar[j] = v;
            }
        }
    } else {
        if (k + 3 < K) {
            float4 v = *(const float4*)(A + (size_t)(bm + r) * K + k);
            ar[0] = v.x; ar[1] = v.y; ar[2] = v.z; ar[3] = v.w;
        } else {
#pragma unroll
            for (int j = 0; j < 4; j++)
                ar[j] = (k + j < K) ? A[(size_t)(bm + r) * K + k + j] : 0.f;
        }
    }
}

__device__ __forceinline__ void g_loadW(const float* __restrict__ W,
                                        int bn, int k0, int K, int N, int tid,
                                        float wr[4]) {
    const int kr = tid >> 4;
    const int c0 = (tid & 15) * 4;
    const int k  = k0 + kr;
    if (k < K && bn + c0 + 3 < N) {
        float4 v = *(const float4*)(W + (size_t)k * N + bn + c0);
        wr[0] = v.x; wr[1] = v.y; wr[2] = v.z; wr[3] = v.w;
    } else {
#pragma unroll
        for (int j = 0; j < 4; j++)
            wr[j] = (k < K && bn + c0 + j < N) ? W[(size_t)k * N + bn + c0 + j] : 0.f;
    }
}

__device__ __forceinline__ void s_store(float (*As)[64], float (*Ws)[64],
                                        int tid, const float ar[4], const float wr[4]) {
    const int r  = tid >> 2;
    const int kq = (tid & 3) * 4;
#pragma unroll
    for (int j = 0; j < 4; j++) As[kq + j][r] = ar[j];
    const int kr = tid >> 4;
    const int c0 = (tid & 15) * 4;
    *(float4*)&Ws[kr][c0] = make_float4(wr[0], wr[1], wr[2], wr[3]);
}

template<bool CONCAT>
__device__ __forceinline__ void gemm_core(const float* __restrict__ A,
                                          const float* __restrict__ A2,
                                          const float* __restrict__ W,
                                          const float* __restrict__ bias,
                                          float* __restrict__ C,
                                          int K, int N, int bm, int bn) {
    __shared__ float As[2][16][64];
    __shared__ float Ws[2][16][64];

    const int tid = threadIdx.x;
    const int tx  = tid & 15;
    const int ty  = tid >> 4;

    float acc[4][4];
#pragma unroll
    for (int i = 0; i < 4; i++)
#pragma unroll
        for (int j = 0; j < 4; j++) acc[i][j] = 0.f;

    float ar[4], wr[4];
    g_loadA<CONCAT>(A, A2, bm, 0, K, tid, ar);
    g_loadW(W, bn, 0, K, N, tid, wr);
    s_store(As[0], Ws[0], tid, ar, wr);
    __syncthreads();

    const int nT = (K + 15) >> 4;
    for (int t = 0; t < nT; t++) {
        const int cur = t & 1;
        const bool more = (t + 1 < nT);
        if (more) {
            g_loadA<CONCAT>(A, A2, bm, (t + 1) * 16, K, tid, ar);
            g_loadW(W, bn, (t + 1) * 16, K, N, tid, wr);
        }
#pragma unroll
        for (int k = 0; k < 16; k++) {
            float4 a4 = *(const float4*)&As[cur][k][ty * 4];
            float4 w4 = *(const float4*)&Ws[cur][k][tx * 4];
            acc[0][0] += a4.x * w4.x; acc[0][1] += a4.x * w4.y; acc[0][2] += a4.x * w4.z; acc[0][3] += a4.x * w4.w;
            acc[1][0] += a4.y * w4.x; acc[1][1] += a4.y * w4.y; acc[1][2] += a4.y * w4.z; acc[1][3] += a4.y * w4.w;
            acc[2][0] += a4.z * w4.x; acc[2][1] += a4.z * w4.y; acc[2][2] += a4.z * w4.z; acc[2][3] += a4.z * w4.w;
            acc[3][0] += a4.w * w4.x; acc[3][1] += a4.w * w4.y; acc[3][2] += a4.w * w4.z; acc[3][3] += a4.w * w4.w;
        }
        if (more) {
            s_store(As[cur ^ 1], Ws[cur ^ 1], tid, ar, wr);
            __syncthreads();
        }
    }

#pragma unroll
    for (int i = 0; i < 4; i++) {
        int r = bm + ty * 4 + i;
#pragma unroll
        for (int j = 0; j < 4; j++) {
            int c = bn + tx * 4 + j;
            if (c < N) C[(size_t)r * N + c] = acc[i][j] + bias[c];
        }
    }
}

template<bool CONCAT>
__global__ void __launch_bounds__(256)
gemm_db_kernel(const float* __restrict__ A,
               const float* __restrict__ A2,
               const float* __restrict__ W,
               const float* __restrict__ bias,
               float* __restrict__ C,
               int K, int N) {
    gemm_core<CONCAT>(A, A2, W, bias, C, K, N, blockIdx.y * 64, blockIdx.x * 64);
}

// Fused head GEMMs: P = S@Wp+bp (col tiles 0..5), Kc = S@Wk+bk (6..8).
__global__ void __launch_bounds__(256)
gemm_heads_kernel(const float* __restrict__ S,
                  const float* __restrict__ Wp, const float* __restrict__ bp,
                  const float* __restrict__ Wk, const float* __restrict__ bk) {
    const int ct = blockIdx.x;
    const int bm = blockIdx.y * 64;
    if (ct < 6)
        gemm_core<false>(S, nullptr, Wp, bp, g_P,  HID_, NP_, bm, ct * 64);
    else
        gemm_core<false>(S, nullptr, Wk, bk, g_Kc, HID_, NK_, bm, (ct - 6) * 64);
}

// ---------------- LayerNorm + elu ----------------
__global__ void ln_elu_kernel(const float* __restrict__ g,
                              const float* __restrict__ bb) {
    const int b = blockIdx.x;
    const int t = threadIdx.x;   // 256
    float x = g_H[(size_t)b * HID_ + t];
    float v = x, v2 = x * x;
#pragma unroll
    for (int o = 16; o > 0; o >>= 1) {
        v  += __shfl_xor_sync(0xffffffffu, v,  o);
        v2 += __shfl_xor_sync(0xffffffffu, v2, o);
    }
    __shared__ float s1[8], s2[8];
    int wid = t >> 5, lane = t & 31;
    if (lane == 0) { s1[wid] = v; s2[wid] = v2; }
    __syncthreads();
    float tot = 0.f, tot2 = 0.f;
#pragma unroll
    for (int i = 0; i < 8; i++) { tot += s1[i]; tot2 += s2[i]; }
    float mu  = tot * (1.f / 256.f);
    float var = tot2 * (1.f / 256.f) - mu * mu;
    float y = (x - mu) * rsqrtf(var + 1e-5f) * g[t] + bb[t];
    g_A[(size_t)b * HID_ + t] = (y > 0.f) ? y : expm1f(y);
}

// =====================================================================
// Fused epilogue: heads + knot einsum + fixups + spline.
// One block per batch row, one warp per mixture.
// Spline math: lane owns 2 consecutive r values (weights hoisted).
// Stores: mu staged through smem -> lane-contiguous float4 STGs;
// sigma written directly as warp-uniform coalesced float4 patterns.
// =====================================================================
__global__ void __launch_bounds__(512)
epilogue_kernel(const float* __restrict__ prev_vel,
                const float* __restrict__ intent,
                const float* __restrict__ basis,
                float* __restrict__ out) {
    const int b    = blockIdx.x;
    const int tid  = threadIdx.x;     // 512
    const int m    = tid >> 5;        // warp id = mixture index
    const int lane = tid & 31;
    const int bmix = b * M_ + m;

    __shared__ float basis_s[NB_ * K_ * D_];   // 1152 floats
    __shared__ float pv_s[D_], it_s[D_];
    __shared__ float bw_s[M_][NB_];
    __shared__ float sig_s[M_][D_ + 2];
    __shared__ float knb[M_][K_ * D_];
    __shared__ int   cidx_s[M_][K_];
    __shared__ float stage[M_][384];           // 24 KB: half of mu per warp

    for (int i = tid; i < NB_ * K_ * D_; i += 512) basis_s[i] = basis[i];
    if (tid == 0) {
        float n2 = 0.f, pv[D_];
#pragma unroll
        for (int d = 0; d < D_; d++) { pv[d] = prev_vel[(size_t)b * D_ + d]; n2 += pv[d] * pv[d]; }
        float inv = 1.f / (sqrtf(n2) + 1e-6f);
#pragma unroll
        for (int d = 0; d < D_; d++) {
            pv_s[d] = pv[d] * inv;
            it_s[d] = intent[(size_t)b * D_ + d];
        }
    }
    __syncthreads();

    // ---- heads (lanes 0..22) ----
    float r = 0.f;
    if (lane < 23) r = g_P[(size_t)b * NP_ + m * 23 + lane];
    if (lane == 0) {
        out[OFF_LOGITS + (size_t)bmix] = r;
    } else if (lane <= NB_) {
        float v = tanhf(r);
        bw_s[m][lane - 1] = v;
        out[OFF_BW + (size_t)bmix * NB_ + (lane - 1)] = v;
    } else if (lane < 23) {
        sig_s[m][lane - 1 - NB_] = expf(r) + 0.1f;
    }
    // ---- knot mask (lanes 0..11) ----
    if (lane < K_) cidx_s[m][lane] = 0;
    float mv = 0.f;
    if (lane < K_) {
        float kv = g_Kc[(size_t)b * NK_ + m * K_ + lane];
        float sg = 1.f / (1.f + expf(-kv));
        mv = (lane == 0 || lane == K_ - 1) ? 1.0f : sg;
        out[OFF_MASK + (size_t)bmix * K_ + lane] = mv;
    }
    unsigned bal = __ballot_sync(0xffffffffu, (lane < K_) && (mv > 0.5f));
    if ((lane < K_) && (mv > 0.5f)) {
        int pos = __popc(bal & ((1u << lane) - 1u));
        cidx_s[m][pos] = lane;
    }
    __syncwarp();

    // ---- knots = tanh(raw) @ basis, knot0 subtracted ----
    for (int i = lane; i < K_ * D_; i += 32) {
        int d = i % D_;
        float acc = 0.f, acc0 = 0.f;
#pragma unroll
        for (int n = 0; n < NB_; n++) {
            float bwv = bw_s[m][n];
            acc  += bwv * basis_s[n * (K_ * D_) + i];
            acc0 += bwv * basis_s[n * (K_ * D_) + d];
        }
        knb[m][i] = acc - acc0;
    }
    __syncwarp();

    // ---- knot-1 alignment + last-knot intent shift (lane 0) ----
    if (lane == 0) {
        float n2 = 0.f, fs[D_];
#pragma unroll
        for (int d = 0; d < D_; d++) { fs[d] = knb[m][D_ + d]; n2 += fs[d] * fs[d]; }
        float mag = sqrtf(n2);
        float invm = 1.f / (mag + 1e-6f);
        float al[D_]; float an2 = 0.f;
#pragma unroll
        for (int d = 0; d < D_; d++) {
            float fn = fs[d] * invm;
            al[d] = 0.8f * pv_s[d] + 0.2f * fn;
            an2 += al[d] * al[d];
        }
        float inva = 1.f / (sqrtf(an2) + 1e-6f);
#pragma unroll
        for (int d = 0; d < D_; d++) knb[m][D_ + d] = al[d] * inva * mag;
#pragma unroll
        for (int d = 0; d < D_; d++) knb[m][(K_ - 1) * D_ + d] += 0.5f * it_s[d];
    }
    __syncwarp();

    // ---- Catmull-Rom spline ----
    const int count = __popc(bal);
    const float c1 = (1.0f / 127.0f) * (float)(count - 1);
    const size_t obase = (size_t)bmix * (R_ * D_);   // 768 floats per (b,m)

#pragma unroll
    for (int half = 0; half < 2; half++) {
        const int idx = half * 32 + lane;     // owns r = 2*idx, 2*idx+1
        float va[12];
#pragma unroll
        for (int h = 0; h < 2; h++) {
            const int rr = idx * 2 + h;
            float xs = (float)rr * c1;
            int j = (int)xs;                  // xs >= 0 -> trunc == floor
            if (j > count - 2) j = count - 2;
            if (j < 0) j = 0;
            float u  = xs - (float)j;
            float u2 = u * u, u3 = u2 * u;
            float w0 = 0.5f * (-u3 + 2.f * u2 - u);
            float w1 = 0.5f * (3.f * u3 - 5.f * u2 + 2.f);
            float w2 = 0.5f * (-3.f * u3 + 4.f * u2 + u);
            float w3 = 0.5f * (u3 - u2);
            int i0 = cidx_s[m][(j - 1 > 0) ? j - 1 : 0];
            int i1 = cidx_s[m][j];
            int i2 = cidx_s[m][j + 1];
            int i3 = cidx_s[m][(j + 2 < count - 1) ? j + 2 : count - 1];
            const float* k0 = &knb[m][i0 * D_];
            const float* k1 = &knb[m][i1 * D_];
            const float* k2 = &knb[m][i2 * D_];
            const float* k3 = &knb[m][i3 * D_];
#pragma unroll
            for (int d = 0; d < D_; d++)
                va[h * D_ + d] = w0 * k0[d] + w1 * k1[d] + w2 * k2[d] + w3 * k3[d];
        }
        // stage: smem at lane*12 (flat positions half*384 + lane*12 .. +11)
        float4* st = (float4*)&stage[m][lane * 12];
        st[0] = make_float4(va[0], va[1], va[2],  va[3]);
        st[1] = make_float4(va[4], va[5], va[6],  va[7]);
        st[2] = make_float4(va[8], va[9], va[10], va[11]);
        __syncwarp();
        // stream out lane-contiguous float4s (perfectly coalesced)
        float* dst = out + OFF_MU + obase + (size_t)half * 384;
#pragma unroll
        for (int q = 0; q < 3; q++) {
            int p = lane + 32 * q;            // float4 index within half
            float4 v = *(float4*)&stage[m][p * 4];
            *(float4*)(dst + (size_t)p * 4) = v;
        }
        __syncwarp();
    }

    // ---- sigma: warp-uniform float4 patterns, direct coalesced stores ----
    {
        const float s0 = sig_s[m][0], s1v = sig_s[m][1], s2v = sig_s[m][2];
        const float s3 = sig_s[m][3], s4v = sig_s[m][4], s5v = sig_s[m][5];
        const float4 pat[3] = {
            make_float4(s0,  s1v, s2v, s3),
            make_float4(s4v, s5v, s0,  s1v),
            make_float4(s2v, s3,  s4v, s5v)
        };
        float* dst = out + OFF_SIG + obase;
#pragma unroll
        for (int q = 0; q < 6; q++) {
            int p = lane + 32 * q;            // float4 index 0..191
            int sel = p - (p / 3) * 3;        // p % 3
            *(float4*)(dst + (size_t)p * 4) = pat[sel];
        }
    }
}

// ---------------- launcher ----------------
extern "C" void kernel_launch(void* const* d_in, const int* in_sizes, int n_in,
                              void* d_out, int out_size) {
    (void)in_sizes; (void)n_in; (void)out_size;
    const float* ls     = (const float*)d_in[0];
    const float* intent = (const float*)d_in[1];
    const float* pvel   = (const float*)d_in[2];
    const float* W1     = (const float*)d_in[3];
    const float* b1     = (const float*)d_in[4];
    const float* lng    = (const float*)d_in[5];
    const float* lnb    = (const float*)d_in[6];
    const float* W2     = (const float*)d_in[7];
    const float* b2     = (const float*)d_in[8];
    const float* Wp     = (const float*)d_in[9];
    const float* bp     = (const float*)d_in[10];
    const float* Wk     = (const float*)d_in[11];
    const float* bk     = (const float*)d_in[12];
    const float* basis  = (const float*)d_in[13];
    float* out = (float*)d_out;

    float *pH, *pA, *pS;
    cudaGetSymbolAddress((void**)&pH, g_H);
    cudaGetSymbolAddress((void**)&pA, g_A);
    cudaGetSymbolAddress((void**)&pS, g_S);

    // 1) H = concat(ls, intent) @ W1 + b1
    gemm_db_kernel<true><<<dim3(HID_ / 64, B_SZ / 64), 256>>>(ls, intent, W1, b1, pH, KIN, HID_);
    // 2) A = elu(LN(H))
    ln_elu_kernel<<<B_SZ, 256>>>(lng, lnb);
    // 3) S = A @ W2 + b2
    gemm_db_kernel<false><<<dim3(HID_ / 64, B_SZ / 64), 256>>>(pA, nullptr, W2, b2, pS, HID_, HID_);
    // 4+5) P = S @ Wp + bp  and  Kc = S @ Wk + bk, fused launch
    gemm_heads_kernel<<<dim3(9, B_SZ / 64), 256>>>(pS, Wp, bp, Wk, bk);
    // 6) fused epilogue (heads + knots + spline + all outputs)
    epilogue_kernel<<<B_SZ, 512>>>(pvel, intent, basis, out);
}

// round 9
// speedup vs baseline: 2.5811x; 1.0692x over previous
#include <cuda_runtime.h>
#include <math.h>
#include <stdint.h>

// ---------------- problem constants ----------------
#define B_SZ   4096
#define LATENT 512
#define D_     6
#define M_     16
#define K_     12      // knots
#define NB_    16
#define R_     128
#define HID_   256
#define KIN    518     // LATENT + D
#define NP_    368     // M*(1+NB+D)
#define NK_    192     // M*K

// output layout (tuple flattened in order)
#define OFF_LOGITS 0ull
#define OFF_MU     65536ull
#define OFF_SIG    50397184ull
#define OFF_MASK   100728832ull
#define OFF_BW     101515264ull

// ---------------- scratch (no allocs allowed) ----------------
__device__ float g_H [B_SZ * HID_];  // pre-LN hidden
__device__ float g_A [B_SZ * HID_];  // elu(LN(h))
__device__ float g_S [B_SZ * HID_];  // situation
__device__ float g_P [B_SZ * NP_];   // raw head
__device__ float g_Kc[B_SZ * NK_];   // knot logits

// =====================================================================
// GEMM core v2: C = A[BxK] @ W[KxN] + bias.
// BM=128, BN=64, KT=16, 256 threads, 8x4 microtile, double-buffered.
// Per k-step: 48B smem -> 32 FMA (0.67 FMA/B vs 0.5 before).
// CONCAT=true: A = concat(ls[Bx512], intent[Bx6]) on the fly
// (ls stride 512 keeps float4 loads aligned).
// =====================================================================
template<bool CONCAT>
__device__ __forceinline__ void g_loadA2(const float* __restrict__ A,
                                         const float* __restrict__ A2,
                                         int bm, int k0, int K, int tid,
                                         float ar[8]) {
    const int r0 = tid >> 2;            // 0..63
    const int kq = (tid & 3) * 4;
    const int k  = k0 + kq;
#pragma unroll
    for (int h = 0; h < 2; h++) {
        const int r = bm + r0 + h * 64;
        float* dst = ar + h * 4;
        if (CONCAT) {
            if (k + 3 < LATENT) {
                float4 v = *(const float4*)(A + (size_t)r * LATENT + k);
                dst[0] = v.x; dst[1] = v.y; dst[2] = v.z; dst[3] = v.w;
            } else {
#pragma unroll
                for (int j = 0; j < 4; j++) {
                    int kk = k + j;
                    float v = 0.f;
                    if (kk < KIN)
                        v = (kk < LATENT) ? A [(size_t)r * LATENT + kk]
                                          : A2[(size_t)r * D_ + (kk - LATENT)];
                    dst[j] = v;
                }
            }
        } else {
            if (k + 3 < K) {
                float4 v = *(const float4*)(A + (size_t)r * K + k);
                dst[0] = v.x; dst[1] = v.y; dst[2] = v.z; dst[3] = v.w;
            } else {
#pragma unroll
                for (int j = 0; j < 4; j++)
                    dst[j] = (k + j < K) ? A[(size_t)r * K + k + j] : 0.f;
            }
        }
    }
}

__device__ __forceinline__ void g_loadW2(const float* __restrict__ W,
                                         int bn, int k0, int K, int N, int tid,
                                         float wr[4]) {
    const int kr = tid >> 4;            // 0..15
    const int c0 = (tid & 15) * 4;
    const int k  = k0 + kr;
    if (k < K && bn + c0 + 3 < N) {
        float4 v = *(const float4*)(W + (size_t)k * N + bn + c0);
        wr[0] = v.x; wr[1] = v.y; wr[2] = v.z; wr[3] = v.w;
    } else {
#pragma unroll
        for (int j = 0; j < 4; j++)
            wr[j] = (k < K && bn + c0 + j < N) ? W[(size_t)k * N + bn + c0 + j] : 0.f;
    }
}

__device__ __forceinline__ void s_store2(float (*As)[128], float (*Ws)[64],
                                         int tid, const float ar[8], const float wr[4]) {
    const int r0 = tid >> 2;
    const int kq = (tid & 3) * 4;
#pragma unroll
    for (int h = 0; h < 2; h++)
#pragma unroll
        for (int j = 0; j < 4; j++) As[kq + j][r0 + h * 64] = ar[h * 4 + j];
    const int kr = tid >> 4;
    const int c0 = (tid & 15) * 4;
    *(float4*)&Ws[kr][c0] = make_float4(wr[0], wr[1], wr[2], wr[3]);
}

template<bool CONCAT>
__device__ __forceinline__ void gemm_core2(const float* __restrict__ A,
                                           const float* __restrict__ A2,
                                           const float* __restrict__ W,
                                           const float* __restrict__ bias,
                                           float* __restrict__ C,
                                           int K, int N, int bm, int bn) {
    __shared__ float As[2][16][128];   // 16 KB
    __shared__ float Ws[2][16][64];    //  8 KB

    const int tid = threadIdx.x;
    const int tx  = tid & 15;          // col group (x4)
    const int ty  = tid >> 4;          // row group (x8)

    float acc[8][4];
#pragma unroll
    for (int i = 0; i < 8; i++)
#pragma unroll
        for (int j = 0; j < 4; j++) acc[i][j] = 0.f;

    float ar[8], wr[4];
    g_loadA2<CONCAT>(A, A2, bm, 0, K, tid, ar);
    g_loadW2(W, bn, 0, K, N, tid, wr);
    s_store2(As[0], Ws[0], tid, ar, wr);
    __syncthreads();

    const int nT = (K + 15) >> 4;
    for (int t = 0; t < nT; t++) {
        const int cur = t & 1;
        const bool more = (t + 1 < nT);
        if (more) {
            g_loadA2<CONCAT>(A, A2, bm, (t + 1) * 16, K, tid, ar);
            g_loadW2(W, bn, (t + 1) * 16, K, N, tid, wr);
        }
#pragma unroll
        for (int k = 0; k < 16; k++) {
            float4 a0 = *(const float4*)&As[cur][k][ty * 8];
            float4 a1 = *(const float4*)&As[cur][k][ty * 8 + 4];
            float4 b4 = *(const float4*)&Ws[cur][k][tx * 4];
            acc[0][0] += a0.x * b4.x; acc[0][1] += a0.x * b4.y; acc[0][2] += a0.x * b4.z; acc[0][3] += a0.x * b4.w;
            acc[1][0] += a0.y * b4.x; acc[1][1] += a0.y * b4.y; acc[1][2] += a0.y * b4.z; acc[1][3] += a0.y * b4.w;
            acc[2][0] += a0.z * b4.x; acc[2][1] += a0.z * b4.y; acc[2][2] += a0.z * b4.z; acc[2][3] += a0.z * b4.w;
            acc[3][0] += a0.w * b4.x; acc[3][1] += a0.w * b4.y; acc[3][2] += a0.w * b4.z; acc[3][3] += a0.w * b4.w;
            acc[4][0] += a1.x * b4.x; acc[4][1] += a1.x * b4.y; acc[4][2] += a1.x * b4.z; acc[4][3] += a1.x * b4.w;
            acc[5][0] += a1.y * b4.x; acc[5][1] += a1.y * b4.y; acc[5][2] += a1.y * b4.z; acc[5][3] += a1.y * b4.w;
            acc[6][0] += a1.z * b4.x; acc[6][1] += a1.z * b4.y; acc[6][2] += a1.z * b4.z; acc[6][3] += a1.z * b4.w;
            acc[7][0] += a1.w * b4.x; acc[7][1] += a1.w * b4.y; acc[7][2] += a1.w * b4.z; acc[7][3] += a1.w * b4.w;
        }
        if (more) {
            s_store2(As[cur ^ 1], Ws[cur ^ 1], tid, ar, wr);
            __syncthreads();
        }
    }

    const int c = bn + tx * 4;
    if (c + 3 < N) {
        float4 bsv = *(const float4*)(bias + c);
#pragma unroll
        for (int i = 0; i < 8; i++) {
            int row = bm + ty * 8 + i;
            float4 o = make_float4(acc[i][0] + bsv.x, acc[i][1] + bsv.y,
                                   acc[i][2] + bsv.z, acc[i][3] + bsv.w);
            *(float4*)(C + (size_t)row * N + c) = o;
        }
    } else {
#pragma unroll
        for (int i = 0; i < 8; i++) {
            int row = bm + ty * 8 + i;
#pragma unroll
            for (int j = 0; j < 4; j++)
                if (c + j < N) C[(size_t)row * N + c + j] = acc[i][j] + bias[c + j];
        }
    }
}

template<bool CONCAT>
__global__ void __launch_bounds__(256)
gemm_db_kernel(const float* __restrict__ A,
               const float* __restrict__ A2,
               const float* __restrict__ W,
               const float* __restrict__ bias,
               float* __restrict__ C,
               int K, int N) {
    gemm_core2<CONCAT>(A, A2, W, bias, C, K, N, blockIdx.y * 128, blockIdx.x * 64);
}

// Fused head GEMMs: P = S@Wp+bp (col tiles 0..5), Kc = S@Wk+bk (6..8).
__global__ void __launch_bounds__(256)
gemm_heads_kernel(const float* __restrict__ S,
                  const float* __restrict__ Wp, const float* __restrict__ bp,
                  const float* __restrict__ Wk, const float* __restrict__ bk) {
    const int ct = blockIdx.x;
    const int bm = blockIdx.y * 128;
    if (ct < 6)
        gemm_core2<false>(S, nullptr, Wp, bp, g_P,  HID_, NP_, bm, ct * 64);
    else
        gemm_core2<false>(S, nullptr, Wk, bk, g_Kc, HID_, NK_, bm, (ct - 6) * 64);
}

// ---------------- LayerNorm + elu ----------------
__global__ void ln_elu_kernel(const float* __restrict__ g,
                              const float* __restrict__ bb) {
    const int b = blockIdx.x;
    const int t = threadIdx.x;   // 256
    float x = g_H[(size_t)b * HID_ + t];
    float v = x, v2 = x * x;
#pragma unroll
    for (int o = 16; o > 0; o >>= 1) {
        v  += __shfl_xor_sync(0xffffffffu, v,  o);
        v2 += __shfl_xor_sync(0xffffffffu, v2, o);
    }
    __shared__ float s1[8], s2[8];
    int wid = t >> 5, lane = t & 31;
    if (lane == 0) { s1[wid] = v; s2[wid] = v2; }
    __syncthreads();
    float tot = 0.f, tot2 = 0.f;
#pragma unroll
    for (int i = 0; i < 8; i++) { tot += s1[i]; tot2 += s2[i]; }
    float mu  = tot * (1.f / 256.f);
    float var = tot2 * (1.f / 256.f) - mu * mu;
    float y = (x - mu) * rsqrtf(var + 1e-5f) * g[t] + bb[t];
    g_A[(size_t)b * HID_ + t] = (y > 0.f) ? y : expm1f(y);
}

// =====================================================================
// Fused epilogue: heads + knot einsum + fixups + spline.
// One block per batch row, one warp per mixture; staged coalesced stores.
// =====================================================================
__global__ void __launch_bounds__(512)
epilogue_kernel(const float* __restrict__ prev_vel,
                const float* __restrict__ intent,
                const float* __restrict__ basis,
                float* __restrict__ out) {
    const int b    = blockIdx.x;
    const int tid  = threadIdx.x;     // 512
    const int m    = tid >> 5;        // warp id = mixture index
    const int lane = tid & 31;
    const int bmix = b * M_ + m;

    __shared__ float basis_s[NB_ * K_ * D_];   // 1152 floats
    __shared__ float pv_s[D_], it_s[D_];
    __shared__ float bw_s[M_][NB_];
    __shared__ float sig_s[M_][D_ + 2];
    __shared__ float knb[M_][K_ * D_];
    __shared__ int   cidx_s[M_][K_];
    __shared__ float stage[M_][384];           // 24 KB: half of mu per warp

    for (int i = tid; i < NB_ * K_ * D_; i += 512) basis_s[i] = basis[i];
    if (tid == 0) {
        float n2 = 0.f, pv[D_];
#pragma unroll
        for (int d = 0; d < D_; d++) { pv[d] = prev_vel[(size_t)b * D_ + d]; n2 += pv[d] * pv[d]; }
        float inv = 1.f / (sqrtf(n2) + 1e-6f);
#pragma unroll
        for (int d = 0; d < D_; d++) {
            pv_s[d] = pv[d] * inv;
            it_s[d] = intent[(size_t)b * D_ + d];
        }
    }
    __syncthreads();

    // ---- heads (lanes 0..22) ----
    float r = 0.f;
    if (lane < 23) r = g_P[(size_t)b * NP_ + m * 23 + lane];
    if (lane == 0) {
        out[OFF_LOGITS + (size_t)bmix] = r;
    } else if (lane <= NB_) {
        float v = tanhf(r);
        bw_s[m][lane - 1] = v;
        out[OFF_BW + (size_t)bmix * NB_ + (lane - 1)] = v;
    } else if (lane < 23) {
        sig_s[m][lane - 1 - NB_] = expf(r) + 0.1f;
    }
    // ---- knot mask (lanes 0..11) ----
    if (lane < K_) cidx_s[m][lane] = 0;
    float mv = 0.f;
    if (lane < K_) {
        float kv = g_Kc[(size_t)b * NK_ + m * K_ + lane];
        float sg = 1.f / (1.f + expf(-kv));
        mv = (lane == 0 || lane == K_ - 1) ? 1.0f : sg;
        out[OFF_MASK + (size_t)bmix * K_ + lane] = mv;
    }
    unsigned bal = __ballot_sync(0xffffffffu, (lane < K_) && (mv > 0.5f));
    if ((lane < K_) && (mv > 0.5f)) {
        int pos = __popc(bal & ((1u << lane) - 1u));
        cidx_s[m][pos] = lane;
    }
    __syncwarp();

    // ---- knots = tanh(raw) @ basis, knot0 subtracted ----
    for (int i = lane; i < K_ * D_; i += 32) {
        int d = i % D_;
        float acc = 0.f, acc0 = 0.f;
#pragma unroll
        for (int n = 0; n < NB_; n++) {
            float bwv = bw_s[m][n];
            acc  += bwv * basis_s[n * (K_ * D_) + i];
            acc0 += bwv * basis_s[n * (K_ * D_) + d];
        }
        knb[m][i] = acc - acc0;
    }
    __syncwarp();

    // ---- knot-1 alignment + last-knot intent shift (lane 0) ----
    if (lane == 0) {
        float n2 = 0.f, fs[D_];
#pragma unroll
        for (int d = 0; d < D_; d++) { fs[d] = knb[m][D_ + d]; n2 += fs[d] * fs[d]; }
        float mag = sqrtf(n2);
        float invm = 1.f / (mag + 1e-6f);
        float al[D_]; float an2 = 0.f;
#pragma unroll
        for (int d = 0; d < D_; d++) {
            float fn = fs[d] * invm;
            al[d] = 0.8f * pv_s[d] + 0.2f * fn;
            an2 += al[d] * al[d];
        }
        float inva = 1.f / (sqrtf(an2) + 1e-6f);
#pragma unroll
        for (int d = 0; d < D_; d++) knb[m][D_ + d] = al[d] * inva * mag;
#pragma unroll
        for (int d = 0; d < D_; d++) knb[m][(K_ - 1) * D_ + d] += 0.5f * it_s[d];
    }
    __syncwarp();

    // ---- Catmull-Rom spline ----
    const int count = __popc(bal);
    const float c1 = (1.0f / 127.0f) * (float)(count - 1);
    const size_t obase = (size_t)bmix * (R_ * D_);   // 768 floats per (b,m)

#pragma unroll
    for (int half = 0; half < 2; half++) {
        const int idx = half * 32 + lane;     // owns r = 2*idx, 2*idx+1
        float va[12];
#pragma unroll
        for (int h = 0; h < 2; h++) {
            const int rr = idx * 2 + h;
            float xs = (float)rr * c1;
            int j = (int)xs;                  // xs >= 0 -> trunc == floor
            if (j > count - 2) j = count - 2;
            if (j < 0) j = 0;
            float u  = xs - (float)j;
            float u2 = u * u, u3 = u2 * u;
            float w0 = 0.5f * (-u3 + 2.f * u2 - u);
            float w1 = 0.5f * (3.f * u3 - 5.f * u2 + 2.f);
            float w2 = 0.5f * (-3.f * u3 + 4.f * u2 + u);
            float w3 = 0.5f * (u3 - u2);
            int i0 = cidx_s[m][(j - 1 > 0) ? j - 1 : 0];
            int i1 = cidx_s[m][j];
            int i2 = cidx_s[m][j + 1];
            int i3 = cidx_s[m][(j + 2 < count - 1) ? j + 2 : count - 1];
            const float* k0 = &knb[m][i0 * D_];
            const float* k1 = &knb[m][i1 * D_];
            const float* k2 = &knb[m][i2 * D_];
            const float* k3 = &knb[m][i3 * D_];
#pragma unroll
            for (int d = 0; d < D_; d++)
                va[h * D_ + d] = w0 * k0[d] + w1 * k1[d] + w2 * k2[d] + w3 * k3[d];
        }
        float4* st = (float4*)&stage[m][lane * 12];
        st[0] = make_float4(va[0], va[1], va[2],  va[3]);
        st[1] = make_float4(va[4], va[5], va[6],  va[7]);
        st[2] = make_float4(va[8], va[9], va[10], va[11]);
        __syncwarp();
        float* dst = out + OFF_MU + obase + (size_t)half * 384;
#pragma unroll
        for (int q = 0; q < 3; q++) {
            int p = lane + 32 * q;
            float4 v = *(float4*)&stage[m][p * 4];
            *(float4*)(dst + (size_t)p * 4) = v;
        }
        __syncwarp();
    }

    // ---- sigma: warp-uniform float4 patterns, direct coalesced stores ----
    {
        const float s0 = sig_s[m][0], s1v = sig_s[m][1], s2v = sig_s[m][2];
        const float s3 = sig_s[m][3], s4v = sig_s[m][4], s5v = sig_s[m][5];
        const float4 pat[3] = {
            make_float4(s0,  s1v, s2v, s3),
            make_float4(s4v, s5v, s0,  s1v),
            make_float4(s2v, s3,  s4v, s5v)
        };
        float* dst = out + OFF_SIG + obase;
#pragma unroll
        for (int q = 0; q < 6; q++) {
            int p = lane + 32 * q;
            int sel = p - (p / 3) * 3;
            *(float4*)(dst + (size_t)p * 4) = pat[sel];
        }
    }
}

// ---------------- launcher ----------------
extern "C" void kernel_launch(void* const* d_in, const int* in_sizes, int n_in,
                              void* d_out, int out_size) {
    (void)in_sizes; (void)n_in; (void)out_size;
    const float* ls     = (const float*)d_in[0];
    const float* intent = (const float*)d_in[1];
    const float* pvel   = (const float*)d_in[2];
    const float* W1     = (const float*)d_in[3];
    const float* b1     = (const float*)d_in[4];
    const float* lng    = (const float*)d_in[5];
    const float* lnb    = (const float*)d_in[6];
    const float* W2     = (const float*)d_in[7];
    const float* b2     = (const float*)d_in[8];
    const float* Wp     = (const float*)d_in[9];
    const float* bp     = (const float*)d_in[10];
    const float* Wk     = (const float*)d_in[11];
    const float* bk     = (const float*)d_in[12];
    const float* basis  = (const float*)d_in[13];
    float* out = (float*)d_out;

    float *pH, *pA, *pS;
    cudaGetSymbolAddress((void**)&pH, g_H);
    cudaGetSymbolAddress((void**)&pA, g_A);
    cudaGetSymbolAddress((void**)&pS, g_S);

    // 1) H = concat(ls, intent) @ W1 + b1
    gemm_db_kernel<true><<<dim3(HID_ / 64, B_SZ / 128), 256>>>(ls, intent, W1, b1, pH, KIN, HID_);
    // 2) A = elu(LN(H))
    ln_elu_kernel<<<B_SZ, 256>>>(lng, lnb);
    // 3) S = A @ W2 + b2
    gemm_db_kernel<false><<<dim3(HID_ / 64, B_SZ / 128), 256>>>(pA, nullptr, W2, b2, pS, HID_, HID_);
    // 4+5) P = S @ Wp + bp  and  Kc = S @ Wk + bk, fused launch
    gemm_heads_kernel<<<dim3(9, B_SZ / 128), 256>>>(pS, Wp, bp, Wk, bk);
    // 6) fused epilogue (heads + knots + spline + all outputs)
    epilogue_kernel<<<B_SZ, 512>>>(pvel, intent, basis, out);
}